// round 6
// baseline (speedup 1.0000x reference)
#include <cuda_runtime.h>
#include <math.h>
#include <float.h>

#define NB 2048
#define ND 256
#define NS 64
#define NK 1024
#define TD 512          // 2*D
#define SD (NS*ND)      // 16384
#define BETA 0.25f

// ---------------- device scratch ----------------
__device__ float g_mr[(size_t)NB*SD];
__device__ float g_mi[(size_t)NB*SD];
__device__ float g_gr[NB*ND];
__device__ float g_gi[NB*ND];
__device__ float g_zf[(size_t)NB*TD];
__device__ float g_zh[(size_t)NB*TD];   // tf32 hi of zf
__device__ float g_zl[(size_t)NB*TD];   // tf32 lo of zf
__device__ float g_ch[(size_t)NK*TD];   // tf32 hi of codebook
__device__ float g_cl[(size_t)NK*TD];   // tf32 lo of codebook
__device__ float g_eff[NB*NS];
__device__ float g_ysq[NK];
__device__ float g_pscore[NB*8];
__device__ int   g_pidx[NB*8];
__device__ int   g_hist[NK];
__device__ float g_aux;

// ---------------- helpers ----------------
__device__ __forceinline__ float warp_sum(float v){
    #pragma unroll
    for(int o=16;o;o>>=1) v += __shfl_xor_sync(0xffffffffu, v, o);
    return v;
}
__device__ __forceinline__ float warp_max(float v){
    #pragma unroll
    for(int o=16;o;o>>=1) v = fmaxf(v, __shfl_xor_sync(0xffffffffu, v, o));
    return v;
}
__device__ __forceinline__ float dot4(float4 a, float4 b){
    return a.x*b.x + a.y*b.y + a.z*b.z + a.w*b.w;
}
__device__ __forceinline__ void fma4(float4& acc, float s, float4 v){
    acc.x += s*v.x; acc.y += s*v.y; acc.z += s*v.z; acc.w += s*v.w;
}
__device__ __forceinline__ float4 mix4(float om, float4 a, float e, float4 g){
    float4 r; r.x=om*a.x+e*g.x; r.y=om*a.y+e*g.y; r.z=om*a.z+e*g.z; r.w=om*a.w+e*g.w; return r;
}
__device__ __forceinline__ float h4(float4 v){ return v.x+v.y+v.z+v.w; }
__device__ __forceinline__ float sq4(float4 v, float mu){
    float a=v.x-mu, b=v.y-mu, c=v.z-mu, d=v.w-mu; return a*a+b*b+c*c+d*d;
}
__device__ __forceinline__ float4 lnorm4(float4 v, float mu, float inv, float4 w, float4 b){
    float4 r;
    r.x=(v.x-mu)*inv*w.x+b.x; r.y=(v.y-mu)*inv*w.y+b.y;
    r.z=(v.z-mu)*inv*w.z+b.z; r.w=(v.w-mu)*inv*w.w+b.w; return r;
}
__device__ __forceinline__ float4 zero4(){ float4 z; z.x=z.y=z.z=z.w=0.f; return z; }
__device__ __forceinline__ float to_tf32(float x){
    unsigned u;
    asm("cvt.rna.tf32.f32 %0, %1;" : "=r"(u) : "f"(x));
    return __uint_as_float(u);
}
__device__ __forceinline__ void cp16(void* dst, const void* src){
    unsigned u = (unsigned)__cvta_generic_to_shared(dst);
    asm volatile("cp.async.cg.shared.global [%0], [%1], 16;" :: "r"(u), "l"(src));
}
__device__ __forceinline__ void mma8(float* d, const unsigned* a, const unsigned* b){
    asm volatile("mma.sync.aligned.m16n8k8.row.col.f32.tf32.tf32.f32 "
        "{%0,%1,%2,%3},{%4,%5,%6,%7},{%8,%9},{%0,%1,%2,%3};"
        : "+f"(d[0]),"+f"(d[1]),"+f"(d[2]),"+f"(d[3])
        : "r"(a[0]),"r"(a[1]),"r"(a[2]),"r"(a[3]),"r"(b[0]),"r"(b[1]));
}

// ---------------- copy inputs -> g state ----------------
__global__ void k_copyg(const float* __restrict__ gr, const float* __restrict__ gi){
    int t = blockIdx.x*512 + threadIdx.x;
    g_gr[t] = gr[t];
    g_gi[t] = gi[t];
}

// ---------------- init: ysq, codebook tf32 split, zero hist/aux --------------
__global__ void k_init(const float* __restrict__ cb){
    int gt = blockIdx.x*256 + threadIdx.x;
    int w = gt >> 5, lane = gt & 31;
    const float* row = cb + (size_t)w*TD;
    float p = 0.f;
    for(int j=lane;j<TD;j+=32){
        float c = row[j];
        p += c*c;
        float h = to_tf32(c);
        g_ch[(size_t)w*TD + j] = h;
        g_cl[(size_t)w*TD + j] = to_tf32(c - h);
    }
    p = warp_sum(p);
    if(lane==0) g_ysq[w] = p;
    if(gt < NK) g_hist[gt] = 0;
    if(gt == 0) g_aux = 0.f;
}

// ---------------- write-address net ----------------
__global__ void __launch_bounds__(256) k_addr(const float* __restrict__ aw,
                                              const float* __restrict__ ab,
                                              const float* __restrict__ gw,
                                              const float* __restrict__ gb)
{
    extern __shared__ float sm[];
    float* s_aw   = sm;
    float* s_gw   = sm + 32768;
    float* s_flat = s_gw + 512;
    float* s_log  = s_flat + 512;
    int t = threadIdx.x, wid = t>>5, lane = t&31;

    {
        const float4* a4 = (const float4*)aw; float4* s4 = (float4*)s_aw;
        for(int i=t;i<8192;i+=256) s4[i] = a4[i];
        const float4* g4 = (const float4*)gw; float4* sg = (float4*)s_gw;
        if(t<128) sg[t] = g4[t];
    }
    __syncthreads();

    float ent_acc = 0.f;
    float gbv = gb[0];

    for(int bi=0;bi<8;bi++){
        int b = blockIdx.x*8 + bi;
        s_flat[t]     = g_gr[b*ND + t];
        s_flat[256+t] = g_gi[b*ND + t];
        __syncthreads();

        #pragma unroll
        for(int r=0;r<8;r++){
            int s = wid*8 + r;
            const float* row = s_aw + s*TD;
            float p = 0.f;
            #pragma unroll 4
            for(int j=lane;j<TD;j+=32) p += s_flat[j]*row[j];
            p = warp_sum(p);
            if(lane==0) s_log[s] = p + ab[s];
        }
        __syncthreads();

        if(wid==0){
            float gp = 0.f;
            #pragma unroll 4
            for(int j=lane;j<TD;j+=32) gp += s_flat[j]*s_gw[j];
            gp = warp_sum(gp);
            float gate = 1.f/(1.f + expf(-(gp + gbv)));
            float v0 = s_log[lane], v1 = s_log[lane+32];
            float m  = warp_max(fmaxf(v0,v1));
            float e0 = expf(v0-m), e1 = expf(v1-m);
            float ssum = warp_sum(e0+e1);
            float w0 = e0/ssum, w1 = e1/ssum;
            ent_acc += -(w0*logf(w0+1e-10f)) - (w1*logf(w1+1e-10f));
            float a0=w0, a1=w1; int i0=lane, i1=lane+32;
            float tv[3]; int ti[3];
            #pragma unroll
            for(int p3=0;p3<3;p3++){
                float v; int ix;
                if(a0>a1 || (a0==a1 && i0<i1)){ v=a0; ix=i0; } else { v=a1; ix=i1; }
                #pragma unroll
                for(int o=16;o;o>>=1){
                    float ov = __shfl_xor_sync(0xffffffffu, v, o);
                    int   oi = __shfl_xor_sync(0xffffffffu, ix, o);
                    if(ov>v || (ov==v && oi<ix)){ v=ov; ix=oi; }
                }
                tv[p3]=v; ti[p3]=ix;
                if(i0==ix) a0 = -1.f;
                if(i1==ix) a1 = -1.f;
            }
            float norm = 1.f/(tv[0]+tv[1]+tv[2]+1e-6f);
            float o0=0.f, o1=0.f;
            #pragma unroll
            for(int p3=0;p3<3;p3++){
                if(lane==ti[p3])    o0 = tv[p3]*norm;
                if(lane+32==ti[p3]) o1 = tv[p3]*norm;
            }
            g_eff[b*NS+lane]    = gate*o0;
            g_eff[b*NS+lane+32] = gate*o1;
        }
        __syncthreads();
    }
    if(wid==0){
        float es = warp_sum(ent_acc);
        if(lane==0) atomicAdd(&g_aux, es*(1.f/(float)NB));
    }
}

// ---------------- fused assoc-mem + complex layernorm (256 thr, 4 CTA/SM) ---
__global__ void __launch_bounds__(256,4) k_mem(const float* __restrict__ mr_in,
                                               const float* __restrict__ mi_in,
                                               int first,
                                               const float* __restrict__ lnrw, const float* __restrict__ lnrb,
                                               const float* __restrict__ lniw, const float* __restrict__ lnib,
                                               const float* __restrict__ clns, const float* __restrict__ clnb)
{
    __shared__ float s_g[TD];
    __shared__ float s_sim[NS];
    __shared__ float s_attn[NS];
    __shared__ float s_eff[NS];
    __shared__ float s_part[8*TD];    // per-warp read partials (16KB)
    __shared__ float s_red2[8];
    __shared__ float s_scal[2];

    int b = blockIdx.x, t = threadIdx.x, wid = t>>5, lane = t&31;
    const float* mrs = first ? (mr_in + (size_t)b*SD) : (g_mr + (size_t)b*SD);
    const float* mis = first ? (mi_in + (size_t)b*SD) : (g_mi + (size_t)b*SD);

    s_g[t]     = g_gr[b*ND + t];
    s_g[256+t] = g_gi[b*ND + t];
    if(t<NS) s_eff[t] = g_eff[b*NS+t];
    __syncthreads();

    const float4* sg4 = (const float4*)s_g;
    float4 gg0 = sg4[lane], gg1 = sg4[lane+32];
    float4 hh0 = sg4[64+lane], hh1 = sg4[64+lane+32];

    // -------- phase 1: sim (DRAM stream, 8 rows/warp, batched loads) --------
    float ps[8];
    #pragma unroll
    for(int r=0;r<8;r++){
        int s = wid*8 + r;
        const float4* pr = (const float4*)(mrs + s*ND);
        const float4* pi = (const float4*)(mis + s*ND);
        float4 a0 = pr[lane], a1 = pr[lane+32];
        float4 c0 = pi[lane], c1 = pi[lane+32];
        ps[r] = dot4(a0,gg0) + dot4(a1,gg1) + dot4(c0,hh0) + dot4(c1,hh1);
    }
    #pragma unroll
    for(int r=0;r<8;r++){
        float p = warp_sum(ps[r]);
        if(lane==0) s_sim[wid*8+r] = p;
    }
    __syncthreads();

    // -------- softmax over S=64 (warp 0) --------
    if(wid==0){
        float v0 = s_sim[lane], v1 = s_sim[lane+32];
        float m  = warp_max(fmaxf(v0,v1));
        float e0 = expf(v0-m), e1 = expf(v1-m);
        float ssum = warp_sum(e0+e1);
        s_attn[lane]    = e0/ssum;
        s_attn[lane+32] = e1/ssum;
    }
    __syncthreads();

    // -------- phase 2: read accum + update + per-row LN (L2 re-read) --------
    float4 ar0=zero4(), ar1=zero4(), ai0=zero4(), ai1=zero4();
    #pragma unroll 2
    for(int r=0;r<8;r++){
        int s = wid*8 + r;
        float e = s_eff[s], om = 1.f - e, at = s_attn[s];
        const float4* pr = (const float4*)(mrs + s*ND);
        const float4* pi = (const float4*)(mis + s*ND);
        float4 a0 = pr[lane], a1 = pr[lane+32];
        float4 c0 = pi[lane], c1 = pi[lane+32];
        fma4(ar0, at, a0); fma4(ar1, at, a1);
        fma4(ai0, at, c0); fma4(ai1, at, c1);
        {
            float4 v0 = mix4(om, a0, e, gg0), v1 = mix4(om, a1, e, gg1);
            float mu  = warp_sum(h4(v0)+h4(v1)) * (1.f/ND);
            float var = warp_sum(sq4(v0,mu)+sq4(v1,mu)) * (1.f/ND);
            float inv = 1.f/sqrtf(var + 1e-6f);
            const float4* w4 = (const float4*)lnrw; const float4* b4 = (const float4*)lnrb;
            float4* dst = (float4*)(g_mr + (size_t)b*SD + s*ND);
            dst[lane]    = lnorm4(v0, mu, inv, __ldg(&w4[lane]),    __ldg(&b4[lane]));
            dst[lane+32] = lnorm4(v1, mu, inv, __ldg(&w4[lane+32]), __ldg(&b4[lane+32]));
        }
        {
            float4 v0 = mix4(om, c0, e, hh0), v1 = mix4(om, c1, e, hh1);
            float mu  = warp_sum(h4(v0)+h4(v1)) * (1.f/ND);
            float var = warp_sum(sq4(v0,mu)+sq4(v1,mu)) * (1.f/ND);
            float inv = 1.f/sqrtf(var + 1e-6f);
            const float4* w4 = (const float4*)lniw; const float4* b4 = (const float4*)lnib;
            float4* dst = (float4*)(g_mi + (size_t)b*SD + s*ND);
            dst[lane]    = lnorm4(v0, mu, inv, __ldg(&w4[lane]),    __ldg(&b4[lane]));
            dst[lane+32] = lnorm4(v1, mu, inv, __ldg(&w4[lane+32]), __ldg(&b4[lane+32]));
        }
    }

    // -------- deterministic cross-warp reduce of read partials --------
    {
        float4* sp4 = (float4*)&s_part[wid*TD];
        sp4[lane]    = ar0; sp4[lane+32]    = ar1;
        sp4[64+lane] = ai0; sp4[64+lane+32] = ai1;
    }
    __syncthreads();
    float red0 = 0.f, red1 = 0.f;
    #pragma unroll
    for(int w=0;w<8;w++){ red0 += s_part[w*TD + t]; red1 += s_part[w*TD + 256 + t]; }
    __syncthreads();
    s_part[t] = red0; s_part[256+t] = red1;
    __syncthreads();

    // -------- complex layernorm on z = g + read --------
    float zr = s_g[t]     + s_part[t];
    float zi = s_g[256+t] + s_part[256+t];
    float mag = sqrtf(zr*zr + zi*zi + 1e-8f);
    float p = warp_sum(mag);
    if(lane==0) s_red2[wid] = p;
    __syncthreads();
    if(t==0){
        float m2=0.f;
        #pragma unroll
        for(int i=0;i<8;i++) m2 += s_red2[i];
        s_scal[0] = m2*(1.f/ND);
    }
    __syncthreads();
    float mean = s_scal[0];
    float dvv = (mag-mean)*(mag-mean);
    p = warp_sum(dvv);
    if(lane==0) s_red2[wid] = p;
    __syncthreads();
    if(t==0){
        float v2=0.f;
        #pragma unroll
        for(int i=0;i<8;i++) v2 += s_red2[i];
        s_scal[1] = 1.f/sqrtf(v2*(1.f/(ND-1)) + 1e-4f);
    }
    __syncthreads();
    {
        float nm = (mag-mean)*s_scal[1]*__ldg(&clns[t]) + __ldg(&clnb[t]);
        float h2 = zr*zr + zi*zi;
        float c, s;
        if(h2 > 0.f){ float ih = 1.f/sqrtf(h2); c = zr*ih; s = zi*ih; }
        else { c = 1.f; s = 0.f; }
        float zrv = nm*c, ziv = nm*s;
        size_t base = (size_t)b*TD;
        g_zf[base + t]      = zrv;
        g_zf[base + ND + t] = ziv;
        float h1 = to_tf32(zrv);
        g_zh[base + t]      = h1;
        g_zl[base + t]      = to_tf32(zrv - h1);
        float h2i = to_tf32(ziv);
        g_zh[base + ND + t] = h2i;
        g_zl[base + ND + t] = to_tf32(ziv - h2i);
    }
}

// ---------------- VQ: 3xTF32 tensor-core distance GEMM + argmin -------------
// grid (16, 8): 128x128 tile per CTA, 256 thr = 8 warps (2x4), warp tile 64x32
// dyn smem: 2 stages x 4 arrays x [128][20] floats = 81920 B
#define VQ_PAD 20
#define VQ_STG 2560   // floats per array
__global__ void __launch_bounds__(256) k_vq(){
    extern __shared__ float vsm[];
    int tid = threadIdx.x, lane = tid&31, wid = tid>>5;
    int wm = wid>>2, wn = wid&3;
    int b0 = blockIdx.x*128, k0 = blockIdx.y*128;

    float acc[4][4][4];
    #pragma unroll
    for(int i=0;i<4;i++)
        #pragma unroll
        for(int j=0;j<4;j++){ acc[i][j][0]=0.f; acc[i][j][1]=0.f; acc[i][j][2]=0.f; acc[i][j][3]=0.f; }

    int row0 = (tid*2)>>2,   c40 = ((tid*2)&3)*4;
    int row1 = (tid*2+1)>>2, c41 = ((tid*2+1)&3)*4;

    // prologue: chunk 0 -> stage 0
    {
        float* base = vsm;
        cp16(&base[            row0*VQ_PAD + c40], &g_zh[(size_t)(b0+row0)*TD + c40]);
        cp16(&base[  VQ_STG  + row0*VQ_PAD + c40], &g_zl[(size_t)(b0+row0)*TD + c40]);
        cp16(&base[2*VQ_STG  + row0*VQ_PAD + c40], &g_ch[(size_t)(k0+row0)*TD + c40]);
        cp16(&base[3*VQ_STG  + row0*VQ_PAD + c40], &g_cl[(size_t)(k0+row0)*TD + c40]);
        cp16(&base[            row1*VQ_PAD + c41], &g_zh[(size_t)(b0+row1)*TD + c41]);
        cp16(&base[  VQ_STG  + row1*VQ_PAD + c41], &g_zl[(size_t)(b0+row1)*TD + c41]);
        cp16(&base[2*VQ_STG  + row1*VQ_PAD + c41], &g_ch[(size_t)(k0+row1)*TD + c41]);
        cp16(&base[3*VQ_STG  + row1*VQ_PAD + c41], &g_cl[(size_t)(k0+row1)*TD + c41]);
        asm volatile("cp.async.commit_group;");
    }

    for(int ch=0; ch<32; ch++){
        if(ch < 31){
            float* base = vsm + ((ch+1)&1)*4*VQ_STG;
            int d0 = (ch+1)*16;
            cp16(&base[            row0*VQ_PAD + c40], &g_zh[(size_t)(b0+row0)*TD + d0 + c40]);
            cp16(&base[  VQ_STG  + row0*VQ_PAD + c40], &g_zl[(size_t)(b0+row0)*TD + d0 + c40]);
            cp16(&base[2*VQ_STG  + row0*VQ_PAD + c40], &g_ch[(size_t)(k0+row0)*TD + d0 + c40]);
            cp16(&base[3*VQ_STG  + row0*VQ_PAD + c40], &g_cl[(size_t)(k0+row0)*TD + d0 + c40]);
            cp16(&base[            row1*VQ_PAD + c41], &g_zh[(size_t)(b0+row1)*TD + d0 + c41]);
            cp16(&base[  VQ_STG  + row1*VQ_PAD + c41], &g_zl[(size_t)(b0+row1)*TD + d0 + c41]);
            cp16(&base[2*VQ_STG  + row1*VQ_PAD + c41], &g_ch[(size_t)(k0+row1)*TD + d0 + c41]);
            cp16(&base[3*VQ_STG  + row1*VQ_PAD + c41], &g_cl[(size_t)(k0+row1)*TD + d0 + c41]);
            asm volatile("cp.async.commit_group;");
            asm volatile("cp.async.wait_group 1;");
        } else {
            asm volatile("cp.async.wait_group 0;");
        }
        __syncthreads();

        float* base = vsm + (ch&1)*4*VQ_STG;
        float* Zh = base;
        float* Zl = base +   VQ_STG;
        float* Ch = base + 2*VQ_STG;
        float* Cl = base + 3*VQ_STG;

        #pragma unroll
        for(int kk=0; kk<16; kk+=8){
            int ka = kk + (lane&3);
            unsigned ah[4][4], al[4][4], bh[4][2], bl[4][2];
            #pragma unroll
            for(int m4=0;m4<4;m4++){
                int r = wm*64 + m4*16 + (lane>>2);
                ah[m4][0] = __float_as_uint(Zh[ r   *VQ_PAD + ka  ]);
                ah[m4][1] = __float_as_uint(Zh[(r+8)*VQ_PAD + ka  ]);
                ah[m4][2] = __float_as_uint(Zh[ r   *VQ_PAD + ka+4]);
                ah[m4][3] = __float_as_uint(Zh[(r+8)*VQ_PAD + ka+4]);
                al[m4][0] = __float_as_uint(Zl[ r   *VQ_PAD + ka  ]);
                al[m4][1] = __float_as_uint(Zl[(r+8)*VQ_PAD + ka  ]);
                al[m4][2] = __float_as_uint(Zl[ r   *VQ_PAD + ka+4]);
                al[m4][3] = __float_as_uint(Zl[(r+8)*VQ_PAD + ka+4]);
            }
            #pragma unroll
            for(int n4=0;n4<4;n4++){
                int c = wn*32 + n4*8 + (lane>>2);
                bh[n4][0] = __float_as_uint(Ch[c*VQ_PAD + ka  ]);
                bh[n4][1] = __float_as_uint(Ch[c*VQ_PAD + ka+4]);
                bl[n4][0] = __float_as_uint(Cl[c*VQ_PAD + ka  ]);
                bl[n4][1] = __float_as_uint(Cl[c*VQ_PAD + ka+4]);
            }
            #pragma unroll
            for(int m4=0;m4<4;m4++)
                #pragma unroll
                for(int n4=0;n4<4;n4++){
                    mma8(acc[m4][n4], ah[m4], bh[n4]);
                    mma8(acc[m4][n4], ah[m4], bl[n4]);
                    mma8(acc[m4][n4], al[m4], bh[n4]);
                }
        }
        __syncthreads();
    }

    // -------- epilogue: per-row argmin over this 128-k tile --------
    float* s_val = vsm;                     // [128][4]
    int*   s_idx = (int*)(vsm + 512);       // [128][4]

    float ys[4][2];
    #pragma unroll
    for(int n4=0;n4<4;n4++){
        int c = k0 + wn*32 + n4*8 + (lane&3)*2;
        ys[n4][0] = __ldg(&g_ysq[c]);
        ys[n4][1] = __ldg(&g_ysq[c+1]);
    }

    #pragma unroll
    for(int m4=0;m4<4;m4++){
        float bvA = FLT_MAX, bvB = FLT_MAX; int biA = 0x7fffffff, biB = 0x7fffffff;
        #pragma unroll
        for(int n4=0;n4<4;n4++){
            int cbase = k0 + wn*32 + n4*8 + (lane&3)*2;
            float d0 = ys[n4][0] - 2.f*acc[m4][n4][0];
            float d1 = ys[n4][1] - 2.f*acc[m4][n4][1];
            float d2 = ys[n4][0] - 2.f*acc[m4][n4][2];
            float d3 = ys[n4][1] - 2.f*acc[m4][n4][3];
            if(d0 < bvA){ bvA = d0; biA = cbase;   }
            if(d1 < bvA){ bvA = d1; biA = cbase+1; }
            if(d2 < bvB){ bvB = d2; biB = cbase;   }
            if(d3 < bvB){ bvB = d3; biB = cbase+1; }
        }
        #pragma unroll
        for(int o=1;o<4;o<<=1){
            float ovA = __shfl_xor_sync(0xffffffffu, bvA, o);
            int   oiA = __shfl_xor_sync(0xffffffffu, biA, o);
            if(ovA<bvA || (ovA==bvA && oiA<biA)){ bvA=ovA; biA=oiA; }
            float ovB = __shfl_xor_sync(0xffffffffu, bvB, o);
            int   oiB = __shfl_xor_sync(0xffffffffu, biB, o);
            if(ovB<bvB || (ovB==bvB && oiB<biB)){ bvB=ovB; biB=oiB; }
        }
        if((lane&3)==0){
            int r = wm*64 + m4*16 + (lane>>2);
            s_val[r*4+wn] = bvA;     s_idx[r*4+wn] = biA;
            s_val[(r+8)*4+wn] = bvB; s_idx[(r+8)*4+wn] = biB;
        }
    }
    __syncthreads();
    if(tid < 128){
        float bv = FLT_MAX; int bi = 0x7fffffff;
        #pragma unroll
        for(int j=0;j<4;j++){
            float v = s_val[tid*4+j]; int ix = s_idx[tid*4+j];
            if(v<bv || (v==bv && ix<bi)){ bv=v; bi=ix; }
        }
        g_pscore[(b0+tid)*8 + blockIdx.y] = bv;
        g_pidx  [(b0+tid)*8 + blockIdx.y] = bi;
    }
}

// ---------------- final argmin, gather codebook, loss, histogram -------------
__global__ void __launch_bounds__(256) k_pick(const float* __restrict__ cb){
    int wid = threadIdx.x>>5, lane = threadIdx.x&31;
    int b = blockIdx.x*8 + wid;
    float bv = FLT_MAX; int bi = 0x7fffffff;
    if(lane < 8){ bv = g_pscore[b*8+lane]; bi = g_pidx[b*8+lane]; }
    #pragma unroll
    for(int o=1;o<32;o<<=1){
        float ov = __shfl_xor_sync(0xffffffffu, bv, o);
        int   oi = __shfl_xor_sync(0xffffffffu, bi, o);
        if(ov<bv || (ov==bv && oi<bi)){ bv=ov; bi=oi; }
    }
    bi = __shfl_sync(0xffffffffu, bi, 0);
    const float* row = cb + (size_t)bi*TD;
    float lacc = 0.f;
    for(int j=lane;j<TD;j+=32){
        float c = row[j], z = g_zf[(size_t)b*TD + j];
        float df = c - z; lacc += df*df;
        if(j < ND) g_gr[b*ND + j] = c;
        else       g_gi[b*ND + j - ND] = c;
    }
    lacc = warp_sum(lacc);
    if(lane==0){
        atomicAdd(&g_aux, BETA * lacc * (1.f/TD) * (1.f/NB));
        atomicAdd(&g_hist[bi], 1);
    }
}

// ---------------- codebook-usage entropy + hist reset ----------------
__global__ void __launch_bounds__(1024) k_ent(){
    __shared__ float s_red[32];
    int t = threadIdx.x;
    float pp = (float)g_hist[t] * (1.f/NB);
    float e = -pp * logf(pp + 1e-10f);
    g_hist[t] = 0;
    e = warp_sum(e);
    if((t&31)==0) s_red[t>>5] = e;
    __syncthreads();
    if(t < 32){
        float v = s_red[t];
        v = warp_sum(v);
        if(t==0) g_aux = g_aux + v * (1.f/6.931471805599453f);
    }
}

// ---------------- write output ----------------
__global__ void k_out(float* __restrict__ out, int out_n){
    int t = blockIdx.x*256 + threadIdx.x;
    int b = t >> 9, j = t & 511;
    out[t] = (j < ND) ? g_gr[b*ND + j] : g_gi[b*ND + j - ND];
    if(t == 0 && out_n > NB*TD) out[out_n-1] = g_aux;
}

// =============================================================================
extern "C" void kernel_launch(void* const* d_in, const int* in_sizes, int n_in,
                              void* d_out, int out_size)
{
    const float* gw_real = (const float*)d_in[0];
    const float* gw_imag = (const float*)d_in[1];
    const float* mem_real= (const float*)d_in[2];
    const float* mem_imag= (const float*)d_in[3];
    const float* gate_w  = (const float*)d_in[4];
    const float* gate_b  = (const float*)d_in[5];
    const float* addr_w  = (const float*)d_in[6];
    const float* addr_b  = (const float*)d_in[7];
    const float* lnr_w   = (const float*)d_in[8];
    const float* lnr_b   = (const float*)d_in[9];
    const float* lni_w   = (const float*)d_in[10];
    const float* lni_b   = (const float*)d_in[11];
    const float* cln_s   = (const float*)d_in[12];
    const float* cln_b   = (const float*)d_in[13];
    const float* codebook= (const float*)d_in[14];
    float* out = (float*)d_out;

    const int SMEM_ADDR = (64*512 + 512 + 512 + 64) * 4;
    const int SMEM_VQ   = 2 * 4 * VQ_STG * 4;      // 81920
    static int attr_done = 0;
    if(!attr_done){
        cudaFuncSetAttribute(k_addr, cudaFuncAttributeMaxDynamicSharedMemorySize, SMEM_ADDR);
        cudaFuncSetAttribute(k_vq,   cudaFuncAttributeMaxDynamicSharedMemorySize, SMEM_VQ);
        attr_done = 1;
    }

    k_copyg<<<1024, 512>>>(gw_real, gw_imag);
    k_init <<<128, 256>>>(codebook);

    for(int it=0; it<5; it++){
        k_addr<<<256, 256, SMEM_ADDR>>>(addr_w, addr_b, gate_w, gate_b);
        k_mem <<<NB, 256>>>(mem_real, mem_imag, it==0 ? 1 : 0,
                            lnr_w, lnr_b, lni_w, lni_b, cln_s, cln_b);
        k_vq  <<<dim3(16,8), 256, SMEM_VQ>>>();
        k_pick<<<256, 256>>>(codebook);
        k_ent <<<1, 1024>>>();
    }
    k_out<<<4096, 256>>>(out, out_size);
}

// round 8
// speedup vs baseline: 1.1364x; 1.1364x over previous
#include <cuda_runtime.h>
#include <cuda_bf16.h>
#include <math.h>
#include <float.h>
#include <stdint.h>

#define NB 2048
#define ND 256
#define NS 64
#define NK 1024
#define TD 512          // 2*D
#define SD (NS*ND)      // 16384
#define KX 1536         // 3*TD for bf16x3
#define BETA 0.25f

// ---------------- device scratch ----------------
__device__ float g_mr[(size_t)NB*SD];
__device__ float g_mi[(size_t)NB*SD];
__device__ float g_gr[NB*ND];
__device__ float g_gi[NB*ND];
__device__ float g_zf[(size_t)NB*TD];
__device__ __nv_bfloat16 g_zb[(size_t)NB*KX];   // [zh | zh | zm]
__device__ __nv_bfloat16 g_cbb[(size_t)NK*KX];  // [ch | cm | ch]
__device__ float g_eff[NB*NS];
__device__ float g_ysq[NK];
__device__ float g_pscore[NB*8];
__device__ int   g_pidx[NB*8];
__device__ int   g_hist[5*NK];
__device__ float g_aux;

// ---------------- helpers ----------------
__device__ __forceinline__ float warp_sum(float v){
    #pragma unroll
    for(int o=16;o;o>>=1) v += __shfl_xor_sync(0xffffffffu, v, o);
    return v;
}
__device__ __forceinline__ float warp_max(float v){
    #pragma unroll
    for(int o=16;o;o>>=1) v = fmaxf(v, __shfl_xor_sync(0xffffffffu, v, o));
    return v;
}
__device__ __forceinline__ float dot4(float4 a, float4 b){
    return a.x*b.x + a.y*b.y + a.z*b.z + a.w*b.w;
}
__device__ __forceinline__ void fma4(float4& acc, float s, float4 v){
    acc.x += s*v.x; acc.y += s*v.y; acc.z += s*v.z; acc.w += s*v.w;
}
__device__ __forceinline__ float4 mix4(float om, float4 a, float e, float4 g){
    float4 r; r.x=om*a.x+e*g.x; r.y=om*a.y+e*g.y; r.z=om*a.z+e*g.z; r.w=om*a.w+e*g.w; return r;
}
__device__ __forceinline__ float h4(float4 v){ return v.x+v.y+v.z+v.w; }
__device__ __forceinline__ float sq4(float4 v, float mu){
    float a=v.x-mu, b=v.y-mu, c=v.z-mu, d=v.w-mu; return a*a+b*b+c*c+d*d;
}
__device__ __forceinline__ float4 lnorm4(float4 v, float mu, float inv, float4 w, float4 b){
    float4 r;
    r.x=(v.x-mu)*inv*w.x+b.x; r.y=(v.y-mu)*inv*w.y+b.y;
    r.z=(v.z-mu)*inv*w.z+b.z; r.w=(v.w-mu)*inv*w.w+b.w; return r;
}
__device__ __forceinline__ float4 zero4(){ float4 z; z.x=z.y=z.z=z.w=0.f; return z; }
__device__ __forceinline__ void cp16(void* dst, const void* src){
    unsigned u = (unsigned)__cvta_generic_to_shared(dst);
    asm volatile("cp.async.cg.shared.global [%0], [%1], 16;" :: "r"(u), "l"(src));
}
__device__ __forceinline__ void mma16(float* d, const unsigned* a, const unsigned* b){
    asm volatile("mma.sync.aligned.m16n8k16.row.col.f32.bf16.bf16.f32 "
        "{%0,%1,%2,%3},{%4,%5,%6,%7},{%8,%9},{%0,%1,%2,%3};"
        : "+f"(d[0]),"+f"(d[1]),"+f"(d[2]),"+f"(d[3])
        : "r"(a[0]),"r"(a[1]),"r"(a[2]),"r"(a[3]),"r"(b[0]),"r"(b[1]));
}

// ---------------- copy inputs -> g state ----------------
__global__ void k_copyg(const float* __restrict__ gr, const float* __restrict__ gi){
    int t = blockIdx.x*512 + threadIdx.x;
    g_gr[t] = gr[t];
    g_gi[t] = gi[t];
}

// ---------------- init: ysq, codebook bf16x3 split, zero hist/aux ------------
__global__ void k_init(const float* __restrict__ cb){
    int gt = blockIdx.x*256 + threadIdx.x;     // 32768 threads = 1024 warps
    int w = gt >> 5, lane = gt & 31;
    const float* row = cb + (size_t)w*TD;
    float p = 0.f;
    for(int j=lane;j<TD;j+=32){
        float c = row[j];
        p += c*c;
        __nv_bfloat16 ch = __float2bfloat16_rn(c);
        __nv_bfloat16 cm = __float2bfloat16_rn(c - __bfloat162float(ch));
        size_t base = (size_t)w*KX;
        g_cbb[base + j]        = ch;
        g_cbb[base + 512 + j]  = cm;
        g_cbb[base + 1024 + j] = ch;
    }
    p = warp_sum(p);
    if(lane==0) g_ysq[w] = p;
    if(gt < 5*NK) g_hist[gt] = 0;
    if(gt == 0) g_aux = 0.f;
}

// ---------------- write-address net ----------------
__global__ void __launch_bounds__(256) k_addr(const float* __restrict__ aw,
                                              const float* __restrict__ ab,
                                              const float* __restrict__ gw,
                                              const float* __restrict__ gb)
{
    extern __shared__ float sm[];
    float* s_aw   = sm;
    float* s_gw   = sm + 32768;
    float* s_flat = s_gw + 512;
    float* s_log  = s_flat + 512;
    int t = threadIdx.x, wid = t>>5, lane = t&31;

    {
        const float4* a4 = (const float4*)aw; float4* s4 = (float4*)s_aw;
        for(int i=t;i<8192;i+=256) s4[i] = a4[i];
        const float4* g4 = (const float4*)gw; float4* sg = (float4*)s_gw;
        if(t<128) sg[t] = g4[t];
    }
    __syncthreads();

    float ent_acc = 0.f;
    float gbv = gb[0];

    for(int bi=0;bi<8;bi++){
        int b = blockIdx.x*8 + bi;
        s_flat[t]     = g_gr[b*ND + t];
        s_flat[256+t] = g_gi[b*ND + t];
        __syncthreads();

        #pragma unroll
        for(int r=0;r<8;r++){
            int s = wid*8 + r;
            const float* row = s_aw + s*TD;
            float p = 0.f;
            #pragma unroll 4
            for(int j=lane;j<TD;j+=32) p += s_flat[j]*row[j];
            p = warp_sum(p);
            if(lane==0) s_log[s] = p + ab[s];
        }
        __syncthreads();

        if(wid==0){
            float gp = 0.f;
            #pragma unroll 4
            for(int j=lane;j<TD;j+=32) gp += s_flat[j]*s_gw[j];
            gp = warp_sum(gp);
            float gate = 1.f/(1.f + expf(-(gp + gbv)));
            float v0 = s_log[lane], v1 = s_log[lane+32];
            float m  = warp_max(fmaxf(v0,v1));
            float e0 = expf(v0-m), e1 = expf(v1-m);
            float ssum = warp_sum(e0+e1);
            float w0 = e0/ssum, w1 = e1/ssum;
            ent_acc += -(w0*logf(w0+1e-10f)) - (w1*logf(w1+1e-10f));
            float a0=w0, a1=w1; int i0=lane, i1=lane+32;
            float tv[3]; int ti[3];
            #pragma unroll
            for(int p3=0;p3<3;p3++){
                float v; int ix;
                if(a0>a1 || (a0==a1 && i0<i1)){ v=a0; ix=i0; } else { v=a1; ix=i1; }
                #pragma unroll
                for(int o=16;o;o>>=1){
                    float ov = __shfl_xor_sync(0xffffffffu, v, o);
                    int   oi = __shfl_xor_sync(0xffffffffu, ix, o);
                    if(ov>v || (ov==v && oi<ix)){ v=ov; ix=oi; }
                }
                tv[p3]=v; ti[p3]=ix;
                if(i0==ix) a0 = -1.f;
                if(i1==ix) a1 = -1.f;
            }
            float norm = 1.f/(tv[0]+tv[1]+tv[2]+1e-6f);
            float o0=0.f, o1=0.f;
            #pragma unroll
            for(int p3=0;p3<3;p3++){
                if(lane==ti[p3])    o0 = tv[p3]*norm;
                if(lane+32==ti[p3]) o1 = tv[p3]*norm;
            }
            g_eff[b*NS+lane]    = gate*o0;
            g_eff[b*NS+lane+32] = gate*o1;
        }
        __syncthreads();
    }
    if(wid==0){
        float es = warp_sum(ent_acc);
        if(lane==0) atomicAdd(&g_aux, es*(1.f/(float)NB));
    }
}

// ---------------- fused assoc-mem + complex layernorm (512 thr, 2 CTA/SM) ---
__global__ void __launch_bounds__(512,2) k_mem(const float* __restrict__ mr_in,
                                               const float* __restrict__ mi_in,
                                               int first,
                                               const float* __restrict__ lnrw, const float* __restrict__ lnrb,
                                               const float* __restrict__ lniw, const float* __restrict__ lnib,
                                               const float* __restrict__ clns, const float* __restrict__ clnb)
{
    __shared__ float s_g[TD];
    __shared__ float s_sim[NS];
    __shared__ float s_attn[NS];
    __shared__ float s_eff[NS];
    __shared__ float s_part[16*TD];
    __shared__ float s_red2[16];
    __shared__ float s_scal[2];

    int b = blockIdx.x, t = threadIdx.x, wid = t>>5, lane = t&31;
    const float* mrs = first ? (mr_in + (size_t)b*SD) : (g_mr + (size_t)b*SD);
    const float* mis = first ? (mi_in + (size_t)b*SD) : (g_mi + (size_t)b*SD);

    if(t<ND) s_g[t] = g_gr[b*ND+t]; else s_g[t] = g_gi[b*ND + (t-ND)];
    if(t<NS) s_eff[t] = g_eff[b*NS+t];
    __syncthreads();

    const float4* sg4 = (const float4*)s_g;
    float4 gg0 = sg4[lane], gg1 = sg4[lane+32];
    float4 hh0 = sg4[64+lane], hh1 = sg4[64+lane+32];

    // phase 1: sim
    #pragma unroll
    for(int r=0;r<4;r++){
        int s = wid*4 + r;
        const float4* pr = (const float4*)(mrs + s*ND);
        const float4* pi = (const float4*)(mis + s*ND);
        float4 a0 = pr[lane], a1 = pr[lane+32];
        float4 c0 = pi[lane], c1 = pi[lane+32];
        float p = dot4(a0,gg0) + dot4(a1,gg1) + dot4(c0,hh0) + dot4(c1,hh1);
        p = warp_sum(p);
        if(lane==0) s_sim[s] = p;
    }
    __syncthreads();

    // softmax over S=64
    if(wid==0){
        float v0 = s_sim[lane], v1 = s_sim[lane+32];
        float m  = warp_max(fmaxf(v0,v1));
        float e0 = expf(v0-m), e1 = expf(v1-m);
        float ssum = warp_sum(e0+e1);
        s_attn[lane]    = e0/ssum;
        s_attn[lane+32] = e1/ssum;
    }
    __syncthreads();

    // phase 2: read accum + update + per-row LN (L2 re-read)
    float4 ar0=zero4(), ar1=zero4(), ai0=zero4(), ai1=zero4();
    #pragma unroll
    for(int r=0;r<4;r++){
        int s = wid*4 + r;
        float e = s_eff[s], om = 1.f - e, at = s_attn[s];
        const float4* pr = (const float4*)(mrs + s*ND);
        const float4* pi = (const float4*)(mis + s*ND);
        float4 a0 = pr[lane], a1 = pr[lane+32];
        float4 c0 = pi[lane], c1 = pi[lane+32];
        fma4(ar0, at, a0); fma4(ar1, at, a1);
        fma4(ai0, at, c0); fma4(ai1, at, c1);
        {
            float4 v0 = mix4(om, a0, e, gg0), v1 = mix4(om, a1, e, gg1);
            float mu  = warp_sum(h4(v0)+h4(v1)) * (1.f/ND);
            float var = warp_sum(sq4(v0,mu)+sq4(v1,mu)) * (1.f/ND);
            float inv = 1.f/sqrtf(var + 1e-6f);
            const float4* w4 = (const float4*)lnrw; const float4* b4 = (const float4*)lnrb;
            float4* dst = (float4*)(g_mr + (size_t)b*SD + s*ND);
            dst[lane]    = lnorm4(v0, mu, inv, __ldg(&w4[lane]),    __ldg(&b4[lane]));
            dst[lane+32] = lnorm4(v1, mu, inv, __ldg(&w4[lane+32]), __ldg(&b4[lane+32]));
        }
        {
            float4 v0 = mix4(om, c0, e, hh0), v1 = mix4(om, c1, e, hh1);
            float mu  = warp_sum(h4(v0)+h4(v1)) * (1.f/ND);
            float var = warp_sum(sq4(v0,mu)+sq4(v1,mu)) * (1.f/ND);
            float inv = 1.f/sqrtf(var + 1e-6f);
            const float4* w4 = (const float4*)lniw; const float4* b4 = (const float4*)lnib;
            float4* dst = (float4*)(g_mi + (size_t)b*SD + s*ND);
            dst[lane]    = lnorm4(v0, mu, inv, __ldg(&w4[lane]),    __ldg(&b4[lane]));
            dst[lane+32] = lnorm4(v1, mu, inv, __ldg(&w4[lane+32]), __ldg(&b4[lane+32]));
        }
    }

    // cross-warp reduce of read partials
    {
        float4* sp4 = (float4*)&s_part[wid*TD];
        sp4[lane]    = ar0; sp4[lane+32]    = ar1;
        sp4[64+lane] = ai0; sp4[64+lane+32] = ai1;
    }
    __syncthreads();
    float red = 0.f;
    #pragma unroll
    for(int w=0;w<16;w++) red += s_part[w*TD + t];
    __syncthreads();
    s_part[t] = red;
    __syncthreads();

    // complex layernorm on z = g + read
    float zr=0.f, zi=0.f, mag=0.f;
    if(t < ND){
        zr = s_g[t]    + s_part[t];
        zi = s_g[ND+t] + s_part[ND+t];
        mag = sqrtf(zr*zr + zi*zi + 1e-8f);
    }
    float p = warp_sum(mag);
    if(lane==0) s_red2[wid] = p;
    __syncthreads();
    if(t==0){
        float m2=0.f;
        #pragma unroll
        for(int i=0;i<8;i++) m2 += s_red2[i];
        s_scal[0] = m2*(1.f/ND);
    }
    __syncthreads();
    float mean = s_scal[0];
    float dv = (t<ND) ? (mag-mean)*(mag-mean) : 0.f;
    p = warp_sum(dv);
    if(lane==0) s_red2[wid] = p;
    __syncthreads();
    if(t==0){
        float v2=0.f;
        #pragma unroll
        for(int i=0;i<8;i++) v2 += s_red2[i];
        s_scal[1] = 1.f/sqrtf(v2*(1.f/(ND-1)) + 1e-4f);
    }
    __syncthreads();
    if(t < ND){
        float nm = (mag-mean)*s_scal[1]*__ldg(&clns[t]) + __ldg(&clnb[t]);
        float h2 = zr*zr + zi*zi;
        float c, s;
        if(h2 > 0.f){ float ih = 1.f/sqrtf(h2); c = zr*ih; s = zi*ih; }
        else { c = 1.f; s = 0.f; }
        float zrv = nm*c, ziv = nm*s;
        size_t zfb = (size_t)b*TD;
        g_zf[zfb + t]      = zrv;
        g_zf[zfb + ND + t] = ziv;
        // bf16x3 split:  A row = [zh | zh | zm]
        size_t zbb = (size_t)b*KX;
        __nv_bfloat16 hr = __float2bfloat16_rn(zrv);
        __nv_bfloat16 mr2 = __float2bfloat16_rn(zrv - __bfloat162float(hr));
        g_zb[zbb + t]         = hr;
        g_zb[zbb + 512 + t]   = hr;
        g_zb[zbb + 1024 + t]  = mr2;
        __nv_bfloat16 hi = __float2bfloat16_rn(ziv);
        __nv_bfloat16 mi2 = __float2bfloat16_rn(ziv - __bfloat162float(hi));
        g_zb[zbb + ND + t]        = hi;
        g_zb[zbb + 512 + ND + t]  = hi;
        g_zb[zbb + 1024 + ND + t] = mi2;
    }
}

// ---------------- VQ: bf16 HMMA distance GEMM + argmin ----------------------
// grid (16, 8); 128x128 tile per CTA; 256 thr = 8 warps (2x4); warp 64x32.
// K = 1536 bf16, chunks of 64; smem row stride 144B (conflict-free gathers).
#define VQ_AB    18432            // bytes per array per stage (128*144)
#define VQ_STAGE 36864
__global__ void __launch_bounds__(256) k_vq(){
    extern __shared__ char vsm[];   // 73728 B
    int tid = threadIdx.x, lane = tid&31, wid = tid>>5;
    int g = lane>>2, tig = lane&3;
    int wm = wid>>2, wn = wid&3;
    int b0 = blockIdx.x*128, k0 = blockIdx.y*128;

    float acc[4][4][4];
    #pragma unroll
    for(int i=0;i<4;i++)
        #pragma unroll
        for(int j=0;j<4;j++){ acc[i][j][0]=0.f; acc[i][j][1]=0.f; acc[i][j][2]=0.f; acc[i][j][3]=0.f; }

    // chunk loader: 2048 cp16 per chunk (A:1024, B:1024), 8 per thread
    #define LOAD_CHUNK(ch, stage) do{ \
        _Pragma("unroll") \
        for(int i=0;i<8;i++){ \
            int q   = tid + i*256; \
            int arr = q >> 10; \
            int row = (q >> 3) & 127; \
            int seg = q & 7; \
            char* dst = vsm + (stage)*VQ_STAGE + arr*VQ_AB + row*144 + seg*16; \
            const __nv_bfloat16* src = arr ? \
                &g_cbb[(size_t)(k0+row)*KX + (ch)*64 + seg*8] : \
                &g_zb [(size_t)(b0+row)*KX + (ch)*64 + seg*8]; \
            cp16(dst, src); \
        } \
        asm volatile("cp.async.commit_group;"); \
    }while(0)

    LOAD_CHUNK(0, 0);

    for(int ch=0; ch<24; ch++){
        if(ch < 23){
            LOAD_CHUNK(ch+1, (ch+1)&1);
            asm volatile("cp.async.wait_group 1;");
        } else {
            asm volatile("cp.async.wait_group 0;");
        }
        __syncthreads();

        const char* As = vsm + (ch&1)*VQ_STAGE;
        const char* Bs = As + VQ_AB;

        #pragma unroll
        for(int kk=0;kk<4;kk++){
            unsigned a[4][4], bfr[4][2];
            #pragma unroll
            for(int m4=0;m4<4;m4++){
                int r = wm*64 + m4*16 + g;
                const char* p = As + r*144 + kk*32 + tig*4;
                a[m4][0] = *(const unsigned*)p;
                a[m4][1] = *(const unsigned*)(p + 8*144);
                a[m4][2] = *(const unsigned*)(p + 16);
                a[m4][3] = *(const unsigned*)(p + 8*144 + 16);
            }
            #pragma unroll
            for(int n4=0;n4<4;n4++){
                int c = wn*32 + n4*8 + g;
                const char* p = Bs + c*144 + kk*32 + tig*4;
                bfr[n4][0] = *(const unsigned*)p;
                bfr[n4][1] = *(const unsigned*)(p + 16);
            }
            #pragma unroll
            for(int m4=0;m4<4;m4++)
                #pragma unroll
                for(int n4=0;n4<4;n4++)
                    mma16(acc[m4][n4], a[m4], bfr[n4]);
        }
        __syncthreads();
    }

    // -------- epilogue: per-row argmin over this 128-k tile --------
    float* s_val = (float*)vsm;             // [128][4]
    int*   s_idx = (int*)(vsm + 2048);      // [128][4]

    // cols this thread owns: wn*32 + n4*8 + 2*tig (+1)
    float ys[4][2];
    #pragma unroll
    for(int n4=0;n4<4;n4++){
        int c = k0 + wn*32 + n4*8 + tig*2;
        ys[n4][0] = __ldg(&g_ysq[c]);
        ys[n4][1] = __ldg(&g_ysq[c+1]);
    }

    #pragma unroll
    for(int m4=0;m4<4;m4++){
        // rows: rA = wm*64+m4*16+g (acc[..][0..1]), rB = rA+8 (acc[..][2..3])
        float bvA = FLT_MAX, bvB = FLT_MAX; int biA = 0x7fffffff, biB = 0x7fffffff;
        #pragma unroll
        for(int n4=0;n4<4;n4++){
            int cb0 = k0 + wn*32 + n4*8 + tig*2;
            float d0 = ys[n4][0] - 2.f*acc[m4][n4][0];
            float d1 = ys[n4][1] - 2.f*acc[m4][n4][1];
            float d2 = ys[n4][0] - 2.f*acc[m4][n4][2];
            float d3 = ys[n4][1] - 2.f*acc[m4][n4][3];
            if(d0 < bvA || (d0==bvA && cb0   < biA)){ bvA = d0; biA = cb0;   }
            if(d1 < bvA || (d1==bvA && cb0+1 < biA)){ bvA = d1; biA = cb0+1; }
            if(d2 < bvB || (d2==bvB && cb0   < biB)){ bvB = d2; biB = cb0;   }
            if(d3 < bvB || (d3==bvB && cb0+1 < biB)){ bvB = d3; biB = cb0+1; }
        }
        // reduce across tig (4 lanes in quad)
        #pragma unroll
        for(int o=1;o<4;o<<=1){
            float ovA = __shfl_xor_sync(0xffffffffu, bvA, o);
            int   oiA = __shfl_xor_sync(0xffffffffu, biA, o);
            if(ovA<bvA || (ovA==bvA && oiA<biA)){ bvA=ovA; biA=oiA; }
            float ovB = __shfl_xor_sync(0xffffffffu, bvB, o);
            int   oiB = __shfl_xor_sync(0xffffffffu, biB, o);
            if(ovB<bvB || (ovB==bvB && oiB<biB)){ bvB=ovB; biB=oiB; }
        }
        if(tig==0){
            int rA = wm*64 + m4*16 + g;
            s_val[rA*4+wn]     = bvA; s_idx[rA*4+wn]     = biA;
            s_val[(rA+8)*4+wn] = bvB; s_idx[(rA+8)*4+wn] = biB;
        }
    }
    __syncthreads();
    if(tid < 128){
        float bv = FLT_MAX; int bi = 0x7fffffff;
        #pragma unroll
        for(int j=0;j<4;j++){
            float v = s_val[tid*4+j]; int ix = s_idx[tid*4+j];
            if(v<bv || (v==bv && ix<bi)){ bv=v; bi=ix; }
        }
        g_pscore[(size_t)(b0+tid)*8 + blockIdx.y] = bv;
        g_pidx  [(size_t)(b0+tid)*8 + blockIdx.y] = bi;
    }
    #undef LOAD_CHUNK
}

// ---------------- final argmin, gather codebook, loss, histogram -------------
__global__ void __launch_bounds__(256) k_pick(const float* __restrict__ cb, int it){
    int wid = threadIdx.x>>5, lane = threadIdx.x&31;
    int b = blockIdx.x*8 + wid;
    float bv = FLT_MAX; int bi = 0x7fffffff;
    if(lane < 8){ bv = g_pscore[b*8+lane]; bi = g_pidx[b*8+lane]; }
    #pragma unroll
    for(int o=1;o<32;o<<=1){
        float ov = __shfl_xor_sync(0xffffffffu, bv, o);
        int   oi = __shfl_xor_sync(0xffffffffu, bi, o);
        if(ov<bv || (ov==bv && oi<bi)){ bv=ov; bi=oi; }
    }
    bi = __shfl_sync(0xffffffffu, bi, 0);
    const float* row = cb + (size_t)bi*TD;
    float lacc = 0.f;
    for(int j=lane;j<TD;j+=32){
        float c = row[j], z = g_zf[(size_t)b*TD + j];
        float df = c - z; lacc += df*df;
        if(j < ND) g_gr[b*ND + j] = c;
        else       g_gi[b*ND + j - ND] = c;
    }
    lacc = warp_sum(lacc);
    if(lane==0){
        atomicAdd(&g_aux, BETA * lacc * (1.f/TD) * (1.f/NB));
        atomicAdd(&g_hist[it*NK + bi], 1);
    }
}

// ---------------- codebook-usage entropy (all 5 iterations) ------------------
__global__ void __launch_bounds__(1024) k_ent5(){
    __shared__ float s_red[32];
    int t = threadIdx.x;
    float e = 0.f;
    #pragma unroll
    for(int it=0;it<5;it++){
        float pp = (float)g_hist[it*NK + t] * (1.f/NB);
        e += -pp * logf(pp + 1e-10f);
    }
    e = warp_sum(e);
    if((t&31)==0) s_red[t>>5] = e;
    __syncthreads();
    if(t < 32){
        float v = s_red[t];
        v = warp_sum(v);
        if(t==0) g_aux = g_aux + v * (1.f/6.931471805599453f);  // /log(1024)
    }
}

// ---------------- write output ----------------
__global__ void k_out(float* __restrict__ out, int out_n){
    int t = blockIdx.x*256 + threadIdx.x;
    int b = t >> 9, j = t & 511;
    out[t] = (j < ND) ? g_gr[b*ND + j] : g_gi[b*ND + j - ND];
    if(t == 0 && out_n > NB*TD) out[out_n-1] = g_aux;
}

// =============================================================================
extern "C" void kernel_launch(void* const* d_in, const int* in_sizes, int n_in,
                              void* d_out, int out_size)
{
    const float* gw_real = (const float*)d_in[0];
    const float* gw_imag = (const float*)d_in[1];
    const float* mem_real= (const float*)d_in[2];
    const float* mem_imag= (const float*)d_in[3];
    const float* gate_w  = (const float*)d_in[4];
    const float* gate_b  = (const float*)d_in[5];
    const float* addr_w  = (const float*)d_in[6];
    const float* addr_b  = (const float*)d_in[7];
    const float* lnr_w   = (const float*)d_in[8];
    const float* lnr_b   = (const float*)d_in[9];
    const float* lni_w   = (const float*)d_in[10];
    const float* lni_b   = (const float*)d_in[11];
    const float* cln_s   = (const float*)d_in[12];
    const float* cln_b   = (const float*)d_in[13];
    const float* codebook= (const float*)d_in[14];
    float* out = (float*)d_out;

    const int SMEM_ADDR = (64*512 + 512 + 512 + 64) * 4;
    const int SMEM_VQ   = 2*VQ_STAGE;               // 73728
    static int attr_done = 0;
    if(!attr_done){
        cudaFuncSetAttribute(k_addr, cudaFuncAttributeMaxDynamicSharedMemorySize, SMEM_ADDR);
        cudaFuncSetAttribute(k_vq,   cudaFuncAttributeMaxDynamicSharedMemorySize, SMEM_VQ);
        attr_done = 1;
    }

    k_copyg<<<1024, 512>>>(gw_real, gw_imag);
    k_init <<<128, 256>>>(codebook);

    for(int it=0; it<5; it++){
        k_addr<<<256, 256, SMEM_ADDR>>>(addr_w, addr_b, gate_w, gate_b);
        k_mem <<<NB, 512>>>(mem_real, mem_imag, it==0 ? 1 : 0,
                            lnr_w, lnr_b, lni_w, lni_b, cln_s, cln_b);
        k_vq  <<<dim3(16,8), 256, SMEM_VQ>>>();
        k_pick<<<256, 256>>>(codebook, it);
    }
    k_ent5<<<1, 1024>>>();
    k_out<<<4096, 256>>>(out, out_size);
}

// round 10
// speedup vs baseline: 1.4161x; 1.2461x over previous
#include <cuda_runtime.h>
#include <cuda_bf16.h>
#include <math.h>
#include <float.h>
#include <stdint.h>

#define NB 2048
#define ND 256
#define NS 64
#define NK 1024
#define TD 512          // 2*D
#define SD (NS*ND)      // 16384
#define KX 1536         // 3*TD for bf16x3
#define BETA 0.25f

// ---------------- device scratch ----------------
__device__ float g_mr[(size_t)NB*SD];
__device__ float g_mi[(size_t)NB*SD];
__device__ float g_gr[NB*ND];
__device__ float g_gi[NB*ND];
__device__ float g_zf[(size_t)NB*TD];
__device__ __nv_bfloat16 g_zb[(size_t)NB*KX];   // [zh | zh | zm]
__device__ __nv_bfloat16 g_cbb[(size_t)NK*KX];  // [ch | cm | ch]
__device__ float g_eff[NB*NS];
__device__ float g_ysq[NK];
__device__ float g_alog[NK*65];                 // precomputed addr/gate logits per codeword
__device__ int   g_idx[NB];
__device__ float g_pscore[NB*8];
__device__ int   g_pidx[NB*8];
__device__ int   g_hist[5*NK];
__device__ float g_aux;

// ---------------- helpers ----------------
__device__ __forceinline__ float warp_sum(float v){
    #pragma unroll
    for(int o=16;o;o>>=1) v += __shfl_xor_sync(0xffffffffu, v, o);
    return v;
}
__device__ __forceinline__ float warp_max(float v){
    #pragma unroll
    for(int o=16;o;o>>=1) v = fmaxf(v, __shfl_xor_sync(0xffffffffu, v, o));
    return v;
}
__device__ __forceinline__ float dot4(float4 a, float4 b){
    return a.x*b.x + a.y*b.y + a.z*b.z + a.w*b.w;
}
__device__ __forceinline__ void fma4(float4& acc, float s, float4 v){
    acc.x += s*v.x; acc.y += s*v.y; acc.z += s*v.z; acc.w += s*v.w;
}
__device__ __forceinline__ void scl4(float4& acc, float s){
    acc.x *= s; acc.y *= s; acc.z *= s; acc.w *= s;
}
__device__ __forceinline__ float4 mix4(float om, float4 a, float e, float4 g){
    float4 r; r.x=om*a.x+e*g.x; r.y=om*a.y+e*g.y; r.z=om*a.z+e*g.z; r.w=om*a.w+e*g.w; return r;
}
__device__ __forceinline__ float h4(float4 v){ return v.x+v.y+v.z+v.w; }
__device__ __forceinline__ float sq4(float4 v, float mu){
    float a=v.x-mu, b=v.y-mu, c=v.z-mu, d=v.w-mu; return a*a+b*b+c*c+d*d;
}
__device__ __forceinline__ float4 lnorm4(float4 v, float mu, float inv, float4 w, float4 b){
    float4 r;
    r.x=(v.x-mu)*inv*w.x+b.x; r.y=(v.y-mu)*inv*w.y+b.y;
    r.z=(v.z-mu)*inv*w.z+b.z; r.w=(v.w-mu)*inv*w.w+b.w; return r;
}
__device__ __forceinline__ float4 zero4(){ float4 z; z.x=z.y=z.z=z.w=0.f; return z; }
__device__ __forceinline__ void cp16(void* dst, const void* src){
    unsigned u = (unsigned)__cvta_generic_to_shared(dst);
    asm volatile("cp.async.cg.shared.global [%0], [%1], 16;" :: "r"(u), "l"(src));
}
__device__ __forceinline__ void mma16(float* d, const unsigned* a, const unsigned* b){
    asm volatile("mma.sync.aligned.m16n8k16.row.col.f32.bf16.bf16.f32 "
        "{%0,%1,%2,%3},{%4,%5,%6,%7},{%8,%9},{%0,%1,%2,%3};"
        : "+f"(d[0]),"+f"(d[1]),"+f"(d[2]),"+f"(d[3])
        : "r"(a[0]),"r"(a[1]),"r"(a[2]),"r"(a[3]),"r"(b[0]),"r"(b[1]));
}

// ---------------- softmax/top3/eff for one b (warp-collective) ---------------
// lane holds logits v0 (s=lane) and v1 (s=lane+32); gate already computed.
// Returns this lane's PARTIAL entropy (2 of 64 slots) — caller must warp_sum.
__device__ __forceinline__ float addr_finish(int b, float v0, float v1, float gate, int lane){
    float m  = warp_max(fmaxf(v0,v1));
    float e0 = expf(v0-m), e1 = expf(v1-m);
    float ssum = warp_sum(e0+e1);
    float w0 = e0/ssum, w1 = e1/ssum;
    float ent = -(w0*logf(w0+1e-10f)) - (w1*logf(w1+1e-10f));
    float a0=w0, a1=w1; int i0=lane, i1=lane+32;
    float tv[3]; int ti[3];
    #pragma unroll
    for(int p3=0;p3<3;p3++){
        float v; int ix;
        if(a0>a1 || (a0==a1 && i0<i1)){ v=a0; ix=i0; } else { v=a1; ix=i1; }
        #pragma unroll
        for(int o=16;o;o>>=1){
            float ov = __shfl_xor_sync(0xffffffffu, v, o);
            int   oi = __shfl_xor_sync(0xffffffffu, ix, o);
            if(ov>v || (ov==v && oi<ix)){ v=ov; ix=oi; }
        }
        tv[p3]=v; ti[p3]=ix;
        if(i0==ix) a0 = -1.f;
        if(i1==ix) a1 = -1.f;
    }
    float norm = 1.f/(tv[0]+tv[1]+tv[2]+1e-6f);
    float o0=0.f, o1=0.f;
    #pragma unroll
    for(int p3=0;p3<3;p3++){
        if(lane==ti[p3])    o0 = tv[p3]*norm;
        if(lane+32==ti[p3]) o1 = tv[p3]*norm;
    }
    g_eff[b*NS+lane]    = gate*o0;
    g_eff[b*NS+lane+32] = gate*o1;
    return ent;
}

// ---------------- copy inputs -> g state ----------------
__global__ void k_copyg(const float* __restrict__ gr, const float* __restrict__ gi){
    int t = blockIdx.x*512 + threadIdx.x;
    g_gr[t] = gr[t];
    g_gi[t] = gi[t];
}

// ---------------- init: ysq, codebook bf16x3 split, zero hist/aux ------------
__global__ void k_init(const float* __restrict__ cb){
    int gt = blockIdx.x*256 + threadIdx.x;     // 32768 threads = 1024 warps
    int w = gt >> 5, lane = gt & 31;
    const float* row = cb + (size_t)w*TD;
    float p = 0.f;
    for(int j=lane;j<TD;j+=32){
        float c = row[j];
        p += c*c;
        __nv_bfloat16 ch = __float2bfloat16_rn(c);
        __nv_bfloat16 cm = __float2bfloat16_rn(c - __bfloat162float(ch));
        size_t base = (size_t)w*KX;
        g_cbb[base + j]        = ch;
        g_cbb[base + 512 + j]  = cm;
        g_cbb[base + 1024 + j] = ch;
    }
    p = warp_sum(p);
    if(lane==0) g_ysq[w] = p;
    if(gt < 5*NK) g_hist[gt] = 0;
    if(gt == 0) g_aux = 0.f;
}

// ---------------- init2: precompute codebook @ [addr_w | gate_w] -------------
__global__ void __launch_bounds__(256) k_init2(const float* __restrict__ cb,
                                               const float* __restrict__ aw,
                                               const float* __restrict__ ab,
                                               const float* __restrict__ gw,
                                               const float* __restrict__ gb){
    int gt = blockIdx.x*256 + threadIdx.x;     // 128 CTAs -> 1024 warps
    int k = gt >> 5, lane = gt & 31;
    const float* crow = cb + (size_t)k*TD;
    float cv[16];
    #pragma unroll
    for(int i=0;i<16;i++) cv[i] = crow[lane + i*32];
    for(int s=0;s<NS;s++){
        const float* wrow = aw + (size_t)s*TD;
        float p = 0.f;
        #pragma unroll
        for(int i=0;i<16;i++) p += cv[i]*__ldg(&wrow[lane + i*32]);
        p = warp_sum(p);
        if(lane==0) g_alog[k*65 + s] = p + ab[s];
    }
    {
        float p = 0.f;
        #pragma unroll
        for(int i=0;i<16;i++) p += cv[i]*__ldg(&gw[lane + i*32]);
        p = warp_sum(p);
        if(lane==0) g_alog[k*65 + 64] = p + gb[0];
    }
}

// ---------------- write-address net (iter 0 — full GEMV path) ----------------
__global__ void __launch_bounds__(256) k_addr(const float* __restrict__ aw,
                                              const float* __restrict__ ab,
                                              const float* __restrict__ gw,
                                              const float* __restrict__ gb)
{
    extern __shared__ float sm[];
    float* s_aw   = sm;
    float* s_gw   = sm + 32768;
    float* s_flat = s_gw + 512;
    float* s_log  = s_flat + 512;
    int t = threadIdx.x, wid = t>>5, lane = t&31;

    {
        const float4* a4 = (const float4*)aw; float4* s4 = (float4*)s_aw;
        for(int i=t;i<8192;i+=256) s4[i] = a4[i];
        const float4* g4 = (const float4*)gw; float4* sg = (float4*)s_gw;
        if(t<128) sg[t] = g4[t];
    }
    __syncthreads();

    float ent_acc = 0.f;
    float gbv = gb[0];

    for(int bi=0;bi<8;bi++){
        int b = blockIdx.x*8 + bi;
        s_flat[t]     = g_gr[b*ND + t];
        s_flat[256+t] = g_gi[b*ND + t];
        __syncthreads();

        #pragma unroll
        for(int r=0;r<8;r++){
            int s = wid*8 + r;
            const float* row = s_aw + s*TD;
            float p = 0.f;
            #pragma unroll 4
            for(int j=lane;j<TD;j+=32) p += s_flat[j]*row[j];
            p = warp_sum(p);
            if(lane==0) s_log[s] = p + ab[s];
        }
        __syncthreads();

        if(wid==0){
            float gp = 0.f;
            #pragma unroll 4
            for(int j=lane;j<TD;j+=32) gp += s_flat[j]*s_gw[j];
            gp = warp_sum(gp);
            float gate = 1.f/(1.f + expf(-(gp + gbv)));
            ent_acc += addr_finish(b, s_log[lane], s_log[lane+32], gate, lane);
        }
        __syncthreads();
    }
    if(wid==0){
        float es = warp_sum(ent_acc);
        if(lane==0) atomicAdd(&g_aux, es*(1.f/(float)NB));
    }
}

// ---------------- write-address net (iters 1-4 — table lookup path) ----------
__global__ void __launch_bounds__(256) k_addr_fast(){
    int t = threadIdx.x, wid = t>>5, lane = t&31;
    int b = blockIdx.x*8 + wid;
    int k = g_idx[b];
    const float* row = g_alog + k*65;
    float v0 = row[lane], v1 = row[lane+32];
    float gl = row[64];
    float gate = 1.f/(1.f + expf(-gl));
    float ent = warp_sum(addr_finish(b, v0, v1, gate, lane));   // FIX: full-warp entropy
    __shared__ float s_e[8];
    if(lane==0) s_e[wid] = ent;
    __syncthreads();
    if(t==0){
        float es = 0.f;
        #pragma unroll
        for(int i=0;i<8;i++) es += s_e[i];
        atomicAdd(&g_aux, es*(1.f/(float)NB));
    }
}

// ---- fused assoc-mem (single pass, online softmax) + complex layernorm ------
__global__ void __launch_bounds__(512,2) k_mem(const float* __restrict__ mr_in,
                                               const float* __restrict__ mi_in,
                                               int first,
                                               const float* __restrict__ lnrw, const float* __restrict__ lnrb,
                                               const float* __restrict__ lniw, const float* __restrict__ lnib,
                                               const float* __restrict__ clns, const float* __restrict__ clnb)
{
    __shared__ float s_g[TD];
    __shared__ float s_eff[NS];
    __shared__ float s_part[16*TD];
    __shared__ float s_wm[16];
    __shared__ float s_ws[16];
    __shared__ float s_wscale[17];     // [0..15] per-warp scale, [16] 1/total
    __shared__ float s_red2[16];
    __shared__ float s_scal[2];

    int b = blockIdx.x, t = threadIdx.x, wid = t>>5, lane = t&31;
    const float* mrs = first ? (mr_in + (size_t)b*SD) : (g_mr + (size_t)b*SD);
    const float* mis = first ? (mi_in + (size_t)b*SD) : (g_mi + (size_t)b*SD);

    if(t<ND) s_g[t] = g_gr[b*ND+t]; else s_g[t] = g_gi[b*ND + (t-ND)];
    if(t<NS) s_eff[t] = g_eff[b*NS+t];
    __syncthreads();

    const float4* sg4 = (const float4*)s_g;
    float4 gg0 = sg4[lane], gg1 = sg4[lane+32];
    float4 hh0 = sg4[64+lane], hh1 = sg4[64+lane+32];

    // single pass: per-warp online softmax accumulation + update + LN + store
    float4 ar0=zero4(), ar1=zero4(), ai0=zero4(), ai1=zero4();
    float om_m = -FLT_MAX, om_s = 0.f;

    #pragma unroll
    for(int r=0;r<4;r++){
        int s = wid*4 + r;
        const float4* pr = (const float4*)(mrs + s*ND);
        const float4* pi = (const float4*)(mis + s*ND);
        float4 a0 = pr[lane], a1 = pr[lane+32];
        float4 c0 = pi[lane], c1 = pi[lane+32];

        // sim for this row (all lanes get value)
        float sim = warp_sum(dot4(a0,gg0) + dot4(a1,gg1) + dot4(c0,hh0) + dot4(c1,hh1));

        // online softmax rescale + accumulate (OLD memory)
        float mnew = fmaxf(om_m, sim);
        float scale = expf(om_m - mnew);       // 0 on first row
        float w = expf(sim - mnew);
        scl4(ar0, scale); scl4(ar1, scale); scl4(ai0, scale); scl4(ai1, scale);
        fma4(ar0, w, a0); fma4(ar1, w, a1);
        fma4(ai0, w, c0); fma4(ai1, w, c1);
        om_s = om_s*scale + w;
        om_m = mnew;

        // memory update + per-row LN + store (needs only eff)
        float e = s_eff[s], om = 1.f - e;
        {
            float4 v0 = mix4(om, a0, e, gg0), v1 = mix4(om, a1, e, gg1);
            float mu  = warp_sum(h4(v0)+h4(v1)) * (1.f/ND);
            float var = warp_sum(sq4(v0,mu)+sq4(v1,mu)) * (1.f/ND);
            float inv = 1.f/sqrtf(var + 1e-6f);
            const float4* w4 = (const float4*)lnrw; const float4* b4 = (const float4*)lnrb;
            float4* dst = (float4*)(g_mr + (size_t)b*SD + s*ND);
            dst[lane]    = lnorm4(v0, mu, inv, __ldg(&w4[lane]),    __ldg(&b4[lane]));
            dst[lane+32] = lnorm4(v1, mu, inv, __ldg(&w4[lane+32]), __ldg(&b4[lane+32]));
        }
        {
            float4 v0 = mix4(om, c0, e, hh0), v1 = mix4(om, c1, e, hh1);
            float mu  = warp_sum(h4(v0)+h4(v1)) * (1.f/ND);
            float var = warp_sum(sq4(v0,mu)+sq4(v1,mu)) * (1.f/ND);
            float inv = 1.f/sqrtf(var + 1e-6f);
            const float4* w4 = (const float4*)lniw; const float4* b4 = (const float4*)lnib;
            float4* dst = (float4*)(g_mi + (size_t)b*SD + s*ND);
            dst[lane]    = lnorm4(v0, mu, inv, __ldg(&w4[lane]),    __ldg(&b4[lane]));
            dst[lane+32] = lnorm4(v1, mu, inv, __ldg(&w4[lane+32]), __ldg(&b4[lane+32]));
        }
    }

    // stash per-warp accum + online stats
    {
        float4* sp4 = (float4*)&s_part[wid*TD];
        sp4[lane]    = ar0; sp4[lane+32]    = ar1;
        sp4[64+lane] = ai0; sp4[64+lane+32] = ai1;
        if(lane==0){ s_wm[wid] = om_m; s_ws[wid] = om_s; }
    }
    __syncthreads();

    // warp 0: global max, per-warp scales, 1/total
    if(wid==0 && lane==0){
        float M = -FLT_MAX;
        #pragma unroll
        for(int w=0;w<16;w++) M = fmaxf(M, s_wm[w]);
        float total = 0.f;
        #pragma unroll
        for(int w=0;w<16;w++){
            float sc = expf(s_wm[w] - M);
            s_wscale[w] = sc;
            total += s_ws[w]*sc;
        }
        s_wscale[16] = 1.f/total;
    }
    __syncthreads();

    // combine: read[t] = (Σ_w scale_w * part_w[t]) / total
    float invt = s_wscale[16];
    float red = 0.f;
    #pragma unroll
    for(int w=0;w<16;w++) red += s_wscale[w]*s_part[w*TD + t];
    red *= invt;
    __syncthreads();
    s_part[t] = red;
    __syncthreads();

    // complex layernorm on z = g + read
    float zr=0.f, zi=0.f, mag=0.f;
    if(t < ND){
        zr = s_g[t]    + s_part[t];
        zi = s_g[ND+t] + s_part[ND+t];
        mag = sqrtf(zr*zr + zi*zi + 1e-8f);
    }
    float p = warp_sum(mag);
    if(lane==0) s_red2[wid] = p;
    __syncthreads();
    if(t==0){
        float m2=0.f;
        #pragma unroll
        for(int i=0;i<8;i++) m2 += s_red2[i];
        s_scal[0] = m2*(1.f/ND);
    }
    __syncthreads();
    float mean = s_scal[0];
    float dv = (t<ND) ? (mag-mean)*(mag-mean) : 0.f;
    p = warp_sum(dv);
    if(lane==0) s_red2[wid] = p;
    __syncthreads();
    if(t==0){
        float v2=0.f;
        #pragma unroll
        for(int i=0;i<8;i++) v2 += s_red2[i];
        s_scal[1] = 1.f/sqrtf(v2*(1.f/(ND-1)) + 1e-4f);
    }
    __syncthreads();
    if(t < ND){
        float nm = (mag-mean)*s_scal[1]*__ldg(&clns[t]) + __ldg(&clnb[t]);
        float h2 = zr*zr + zi*zi;
        float c, s;
        if(h2 > 0.f){ float ih = 1.f/sqrtf(h2); c = zr*ih; s = zi*ih; }
        else { c = 1.f; s = 0.f; }
        float zrv = nm*c, ziv = nm*s;
        size_t zfb = (size_t)b*TD;
        g_zf[zfb + t]      = zrv;
        g_zf[zfb + ND + t] = ziv;
        size_t zbb = (size_t)b*KX;
        __nv_bfloat16 hr = __float2bfloat16_rn(zrv);
        __nv_bfloat16 mr2 = __float2bfloat16_rn(zrv - __bfloat162float(hr));
        g_zb[zbb + t]         = hr;
        g_zb[zbb + 512 + t]   = hr;
        g_zb[zbb + 1024 + t]  = mr2;
        __nv_bfloat16 hi = __float2bfloat16_rn(ziv);
        __nv_bfloat16 mi2 = __float2bfloat16_rn(ziv - __bfloat162float(hi));
        g_zb[zbb + ND + t]        = hi;
        g_zb[zbb + 512 + ND + t]  = hi;
        g_zb[zbb + 1024 + ND + t] = mi2;
    }
}

// ---------------- VQ: bf16 HMMA distance GEMM + argmin ----------------------
#define VQ_AB    18432
#define VQ_STAGE 36864
__global__ void __launch_bounds__(256) k_vq(){
    extern __shared__ char vsm[];   // 73728 B
    int tid = threadIdx.x, lane = tid&31, wid = tid>>5;
    int g = lane>>2, tig = lane&3;
    int wm = wid>>2, wn = wid&3;
    int b0 = blockIdx.x*128, k0 = blockIdx.y*128;

    float acc[4][4][4];
    #pragma unroll
    for(int i=0;i<4;i++)
        #pragma unroll
        for(int j=0;j<4;j++){ acc[i][j][0]=0.f; acc[i][j][1]=0.f; acc[i][j][2]=0.f; acc[i][j][3]=0.f; }

    #define LOAD_CHUNK(ch, stage) do{ \
        _Pragma("unroll") \
        for(int i=0;i<8;i++){ \
            int q   = tid + i*256; \
            int arr = q >> 10; \
            int row = (q >> 3) & 127; \
            int seg = q & 7; \
            char* dst = vsm + (stage)*VQ_STAGE + arr*VQ_AB + row*144 + seg*16; \
            const __nv_bfloat16* src = arr ? \
                &g_cbb[(size_t)(k0+row)*KX + (ch)*64 + seg*8] : \
                &g_zb [(size_t)(b0+row)*KX + (ch)*64 + seg*8]; \
            cp16(dst, src); \
        } \
        asm volatile("cp.async.commit_group;"); \
    }while(0)

    LOAD_CHUNK(0, 0);

    for(int ch=0; ch<24; ch++){
        if(ch < 23){
            LOAD_CHUNK(ch+1, (ch+1)&1);
            asm volatile("cp.async.wait_group 1;");
        } else {
            asm volatile("cp.async.wait_group 0;");
        }
        __syncthreads();

        const char* As = vsm + (ch&1)*VQ_STAGE;
        const char* Bs = As + VQ_AB;

        #pragma unroll
        for(int kk=0;kk<4;kk++){
            unsigned a[4][4], bfr[4][2];
            #pragma unroll
            for(int m4=0;m4<4;m4++){
                int r = wm*64 + m4*16 + g;
                const char* p = As + r*144 + kk*32 + tig*4;
                a[m4][0] = *(const unsigned*)p;
                a[m4][1] = *(const unsigned*)(p + 8*144);
                a[m4][2] = *(const unsigned*)(p + 16);
                a[m4][3] = *(const unsigned*)(p + 8*144 + 16);
            }
            #pragma unroll
            for(int n4=0;n4<4;n4++){
                int c = wn*32 + n4*8 + g;
                const char* p = Bs + c*144 + kk*32 + tig*4;
                bfr[n4][0] = *(const unsigned*)p;
                bfr[n4][1] = *(const unsigned*)(p + 16);
            }
            #pragma unroll
            for(int m4=0;m4<4;m4++)
                #pragma unroll
                for(int n4=0;n4<4;n4++)
                    mma16(acc[m4][n4], a[m4], bfr[n4]);
        }
        __syncthreads();
    }

    float* s_val = (float*)vsm;
    int*   s_idx = (int*)(vsm + 2048);

    float ys[4][2];
    #pragma unroll
    for(int n4=0;n4<4;n4++){
        int c = k0 + wn*32 + n4*8 + tig*2;
        ys[n4][0] = __ldg(&g_ysq[c]);
        ys[n4][1] = __ldg(&g_ysq[c+1]);
    }

    #pragma unroll
    for(int m4=0;m4<4;m4++){
        float bvA = FLT_MAX, bvB = FLT_MAX; int biA = 0x7fffffff, biB = 0x7fffffff;
        #pragma unroll
        for(int n4=0;n4<4;n4++){
            int cb0 = k0 + wn*32 + n4*8 + tig*2;
            float d0 = ys[n4][0] - 2.f*acc[m4][n4][0];
            float d1 = ys[n4][1] - 2.f*acc[m4][n4][1];
            float d2 = ys[n4][0] - 2.f*acc[m4][n4][2];
            float d3 = ys[n4][1] - 2.f*acc[m4][n4][3];
            if(d0 < bvA || (d0==bvA && cb0   < biA)){ bvA = d0; biA = cb0;   }
            if(d1 < bvA || (d1==bvA && cb0+1 < biA)){ bvA = d1; biA = cb0+1; }
            if(d2 < bvB || (d2==bvB && cb0   < biB)){ bvB = d2; biB = cb0;   }
            if(d3 < bvB || (d3==bvB && cb0+1 < biB)){ bvB = d3; biB = cb0+1; }
        }
        #pragma unroll
        for(int o=1;o<4;o<<=1){
            float ovA = __shfl_xor_sync(0xffffffffu, bvA, o);
            int   oiA = __shfl_xor_sync(0xffffffffu, biA, o);
            if(ovA<bvA || (ovA==bvA && oiA<biA)){ bvA=ovA; biA=oiA; }
            float ovB = __shfl_xor_sync(0xffffffffu, bvB, o);
            int   oiB = __shfl_xor_sync(0xffffffffu, biB, o);
            if(ovB<bvB || (ovB==bvB && oiB<biB)){ bvB=ovB; biB=oiB; }
        }
        if(tig==0){
            int rA = wm*64 + m4*16 + g;
            s_val[rA*4+wn]     = bvA; s_idx[rA*4+wn]     = biA;
            s_val[(rA+8)*4+wn] = bvB; s_idx[(rA+8)*4+wn] = biB;
        }
    }
    __syncthreads();
    if(tid < 128){
        float bv = FLT_MAX; int bi = 0x7fffffff;
        #pragma unroll
        for(int j=0;j<4;j++){
            float v = s_val[tid*4+j]; int ix = s_idx[tid*4+j];
            if(v<bv || (v==bv && ix<bi)){ bv=v; bi=ix; }
        }
        g_pscore[(size_t)(b0+tid)*8 + blockIdx.y] = bv;
        g_pidx  [(size_t)(b0+tid)*8 + blockIdx.y] = bi;
    }
    #undef LOAD_CHUNK
}

// ---------------- final argmin, gather codebook, loss, histogram -------------
__global__ void __launch_bounds__(256) k_pick(const float* __restrict__ cb, int it){
    int wid = threadIdx.x>>5, lane = threadIdx.x&31;
    int b = blockIdx.x*8 + wid;
    float bv = FLT_MAX; int bi = 0x7fffffff;
    if(lane < 8){ bv = g_pscore[b*8+lane]; bi = g_pidx[b*8+lane]; }
    #pragma unroll
    for(int o=1;o<32;o<<=1){
        float ov = __shfl_xor_sync(0xffffffffu, bv, o);
        int   oi = __shfl_xor_sync(0xffffffffu, bi, o);
        if(ov<bv || (ov==bv && oi<bi)){ bv=ov; bi=oi; }
    }
    bi = __shfl_sync(0xffffffffu, bi, 0);
    const float* row = cb + (size_t)bi*TD;
    float lacc = 0.f;
    for(int j=lane;j<TD;j+=32){
        float c = row[j], z = g_zf[(size_t)b*TD + j];
        float df = c - z; lacc += df*df;
        if(j < ND) g_gr[b*ND + j] = c;
        else       g_gi[b*ND + j - ND] = c;
    }
    lacc = warp_sum(lacc);
    if(lane==0){
        g_idx[b] = bi;
        atomicAdd(&g_aux, BETA * lacc * (1.f/TD) * (1.f/NB));
        atomicAdd(&g_hist[it*NK + bi], 1);
    }
}

// ---------------- codebook-usage entropy (all 5 iterations) ------------------
__global__ void __launch_bounds__(1024) k_ent5(){
    __shared__ float s_red[32];
    int t = threadIdx.x;
    float e = 0.f;
    #pragma unroll
    for(int it=0;it<5;it++){
        float pp = (float)g_hist[it*NK + t] * (1.f/NB);
        e += -pp * logf(pp + 1e-10f);
    }
    e = warp_sum(e);
    if((t&31)==0) s_red[t>>5] = e;
    __syncthreads();
    if(t < 32){
        float v = s_red[t];
        v = warp_sum(v);
        if(t==0) g_aux = g_aux + v * (1.f/6.931471805599453f);  // /log(1024)
    }
}

// ---------------- write output ----------------
__global__ void k_out(float* __restrict__ out, int out_n){
    int t = blockIdx.x*256 + threadIdx.x;
    int b = t >> 9, j = t & 511;
    out[t] = (j < ND) ? g_gr[b*ND + j] : g_gi[b*ND + j - ND];
    if(t == 0 && out_n > NB*TD) out[out_n-1] = g_aux;
}

// =============================================================================
extern "C" void kernel_launch(void* const* d_in, const int* in_sizes, int n_in,
                              void* d_out, int out_size)
{
    const float* gw_real = (const float*)d_in[0];
    const float* gw_imag = (const float*)d_in[1];
    const float* mem_real= (const float*)d_in[2];
    const float* mem_imag= (const float*)d_in[3];
    const float* gate_w  = (const float*)d_in[4];
    const float* gate_b  = (const float*)d_in[5];
    const float* addr_w  = (const float*)d_in[6];
    const float* addr_b  = (const float*)d_in[7];
    const float* lnr_w   = (const float*)d_in[8];
    const float* lnr_b   = (const float*)d_in[9];
    const float* lni_w   = (const float*)d_in[10];
    const float* lni_b   = (const float*)d_in[11];
    const float* cln_s   = (const float*)d_in[12];
    const float* cln_b   = (const float*)d_in[13];
    const float* codebook= (const float*)d_in[14];
    float* out = (float*)d_out;

    const int SMEM_ADDR = (64*512 + 512 + 512 + 64) * 4;
    const int SMEM_VQ   = 2*VQ_STAGE;               // 73728
    static int attr_done = 0;
    if(!attr_done){
        cudaFuncSetAttribute(k_addr, cudaFuncAttributeMaxDynamicSharedMemorySize, SMEM_ADDR);
        cudaFuncSetAttribute(k_vq,   cudaFuncAttributeMaxDynamicSharedMemorySize, SMEM_VQ);
        attr_done = 1;
    }

    k_copyg<<<1024, 512>>>(gw_real, gw_imag);
    k_init <<<128, 256>>>(codebook);
    k_init2<<<128, 256>>>(codebook, addr_w, addr_b, gate_w, gate_b);

    for(int it=0; it<5; it++){
        if(it == 0)
            k_addr<<<256, 256, SMEM_ADDR>>>(addr_w, addr_b, gate_w, gate_b);
        else
            k_addr_fast<<<256, 256>>>();
        k_mem <<<NB, 512>>>(mem_real, mem_imag, it==0 ? 1 : 0,
                            lnr_w, lnr_b, lni_w, lni_b, cln_s, cln_b);
        k_vq  <<<dim3(16,8), 256, SMEM_VQ>>>();
        k_pick<<<256, 256>>>(codebook, it);
    }
    k_ent5<<<1, 1024>>>();
    k_out<<<4096, 256>>>(out, out_size);
}

// round 11
// speedup vs baseline: 1.4976x; 1.0576x over previous
#include <cuda_runtime.h>
#include <cuda_bf16.h>
#include <math.h>
#include <float.h>
#include <stdint.h>

#define NB 2048
#define ND 256
#define NS 64
#define NK 1024
#define TD 512          // 2*D
#define SD (NS*ND)      // 16384
#define KX 1536         // 3*TD for bf16x3
#define BETA 0.25f

// ---------------- device scratch ----------------
__device__ float g_mr[(size_t)NB*SD];
__device__ float g_mi[(size_t)NB*SD];
__device__ float g_gr[NB*ND];
__device__ float g_gi[NB*ND];
__device__ float g_zf[(size_t)NB*TD];
__device__ __nv_bfloat16 g_zb[(size_t)NB*KX];   // [zh | zh | zm]
__device__ __nv_bfloat16 g_cbb[(size_t)NK*KX];  // [ch | cm | ch]
__device__ float g_eff[NB*NS];
__device__ float g_ysq[NK];
__device__ float g_alog[NK*65];                 // codebook @ [addr_w|gate_w]
__device__ float g_blog[NB*65];                 // iter-0 logits
__device__ int   g_idx[NB];
__device__ float g_pscore[NB*16];
__device__ int   g_pidx[NB*16];
__device__ int   g_hist[5*NK];
__device__ float g_aux;

// ---------------- helpers ----------------
__device__ __forceinline__ float warp_sum(float v){
    #pragma unroll
    for(int o=16;o;o>>=1) v += __shfl_xor_sync(0xffffffffu, v, o);
    return v;
}
__device__ __forceinline__ float warp_max(float v){
    #pragma unroll
    for(int o=16;o;o>>=1) v = fmaxf(v, __shfl_xor_sync(0xffffffffu, v, o));
    return v;
}
__device__ __forceinline__ float dot4(float4 a, float4 b){
    return a.x*b.x + a.y*b.y + a.z*b.z + a.w*b.w;
}
__device__ __forceinline__ void fma4(float4& acc, float s, float4 v){
    acc.x += s*v.x; acc.y += s*v.y; acc.z += s*v.z; acc.w += s*v.w;
}
__device__ __forceinline__ void scl4(float4& acc, float s){
    acc.x *= s; acc.y *= s; acc.z *= s; acc.w *= s;
}
__device__ __forceinline__ float4 mix4(float om, float4 a, float e, float4 g){
    float4 r; r.x=om*a.x+e*g.x; r.y=om*a.y+e*g.y; r.z=om*a.z+e*g.z; r.w=om*a.w+e*g.w; return r;
}
__device__ __forceinline__ float h4(float4 v){ return v.x+v.y+v.z+v.w; }
__device__ __forceinline__ float sq4(float4 v, float mu){
    float a=v.x-mu, b=v.y-mu, c=v.z-mu, d=v.w-mu; return a*a+b*b+c*c+d*d;
}
__device__ __forceinline__ float4 lnorm4(float4 v, float mu, float inv, float4 w, float4 b){
    float4 r;
    r.x=(v.x-mu)*inv*w.x+b.x; r.y=(v.y-mu)*inv*w.y+b.y;
    r.z=(v.z-mu)*inv*w.z+b.z; r.w=(v.w-mu)*inv*w.w+b.w; return r;
}
__device__ __forceinline__ float4 zero4(){ float4 z; z.x=z.y=z.z=z.w=0.f; return z; }
__device__ __forceinline__ void cp16(void* dst, const void* src){
    unsigned u = (unsigned)__cvta_generic_to_shared(dst);
    asm volatile("cp.async.cg.shared.global [%0], [%1], 16;" :: "r"(u), "l"(src));
}
__device__ __forceinline__ void mma16(float* d, const unsigned* a, const unsigned* b){
    asm volatile("mma.sync.aligned.m16n8k16.row.col.f32.bf16.bf16.f32 "
        "{%0,%1,%2,%3},{%4,%5,%6,%7},{%8,%9},{%0,%1,%2,%3};"
        : "+f"(d[0]),"+f"(d[1]),"+f"(d[2]),"+f"(d[3])
        : "r"(a[0]),"r"(a[1]),"r"(a[2]),"r"(a[3]),"r"(b[0]),"r"(b[1]));
}

// ---------------- softmax/top3/eff for one b (warp-collective) ---------------
// Returns this lane's PARTIAL entropy — caller must warp_sum.
__device__ __forceinline__ float addr_finish(int b, float v0, float v1, float gate, int lane){
    float m  = warp_max(fmaxf(v0,v1));
    float e0 = expf(v0-m), e1 = expf(v1-m);
    float ssum = warp_sum(e0+e1);
    float w0 = e0/ssum, w1 = e1/ssum;
    float ent = -(w0*logf(w0+1e-10f)) - (w1*logf(w1+1e-10f));
    float a0=w0, a1=w1; int i0=lane, i1=lane+32;
    float tv[3]; int ti[3];
    #pragma unroll
    for(int p3=0;p3<3;p3++){
        float v; int ix;
        if(a0>a1 || (a0==a1 && i0<i1)){ v=a0; ix=i0; } else { v=a1; ix=i1; }
        #pragma unroll
        for(int o=16;o;o>>=1){
            float ov = __shfl_xor_sync(0xffffffffu, v, o);
            int   oi = __shfl_xor_sync(0xffffffffu, ix, o);
            if(ov>v || (ov==v && oi<ix)){ v=ov; ix=oi; }
        }
        tv[p3]=v; ti[p3]=ix;
        if(i0==ix) a0 = -1.f;
        if(i1==ix) a1 = -1.f;
    }
    float norm = 1.f/(tv[0]+tv[1]+tv[2]+1e-6f);
    float o0=0.f, o1=0.f;
    #pragma unroll
    for(int p3=0;p3<3;p3++){
        if(lane==ti[p3])    o0 = tv[p3]*norm;
        if(lane+32==ti[p3]) o1 = tv[p3]*norm;
    }
    g_eff[b*NS+lane]    = gate*o0;
    g_eff[b*NS+lane+32] = gate*o1;
    return ent;
}

// ---------------- copy inputs -> g state ----------------
__global__ void k_copyg(const float* __restrict__ gr, const float* __restrict__ gi){
    int t = blockIdx.x*512 + threadIdx.x;
    g_gr[t] = gr[t];
    g_gi[t] = gi[t];
}

// ---------------- init: ysq, codebook bf16x3 split, zero hist/aux ------------
__global__ void k_init(const float* __restrict__ cb){
    int gt = blockIdx.x*256 + threadIdx.x;
    int w = gt >> 5, lane = gt & 31;
    const float* row = cb + (size_t)w*TD;
    float p = 0.f;
    for(int j=lane;j<TD;j+=32){
        float c = row[j];
        p += c*c;
        __nv_bfloat16 ch = __float2bfloat16_rn(c);
        __nv_bfloat16 cm = __float2bfloat16_rn(c - __bfloat162float(ch));
        size_t base = (size_t)w*KX;
        g_cbb[base + j]        = ch;
        g_cbb[base + 512 + j]  = cm;
        g_cbb[base + 1024 + j] = ch;
    }
    p = warp_sum(p);
    if(lane==0) g_ysq[w] = p;
    if(gt < 5*NK) g_hist[gt] = 0;
    if(gt == 0) g_aux = 0.f;
}

// ---------------- logits GEMM: X @ [addr_w | gate_w]^T + [ab | gb] -----------
// mode 0: X = initial g (g_gr/g_gi, stride ND), M=2048 -> g_blog
// mode 1: X = codebook (stride TD), M=1024 -> g_alog
__global__ void __launch_bounds__(256) k_logits(int mode, const float* __restrict__ cb,
                                                const float* __restrict__ aw,
                                                const float* __restrict__ ab,
                                                const float* __restrict__ gw,
                                                const float* __restrict__ gb){
    __shared__ float s_w[65*65];   // rows padded to 65 (bank-conflict-free)
    __shared__ float s_x[32*64];
    int t = threadIdx.x;
    int ml = t >> 3, ng = t & 7;
    int m0 = blockIdx.x*32;
    float acc[9];
    #pragma unroll
    for(int i=0;i<9;i++) acc[i]=0.f;

    for(int ch=0; ch<8; ch++){
        __syncthreads();
        // weights chunk [65][64]
        for(int idx=t; idx<1040; idx+=256){
            int n = idx>>4, j4 = (idx&15)*4;
            float4 v = (n<64) ? *(const float4*)&aw[(size_t)n*TD + ch*64 + j4]
                              : *(const float4*)&gw[ch*64 + j4];
            s_w[n*65+j4+0]=v.x; s_w[n*65+j4+1]=v.y; s_w[n*65+j4+2]=v.z; s_w[n*65+j4+3]=v.w;
        }
        // x chunk [32][64]
        #pragma unroll
        for(int l=0;l<2;l++){
            int idx = t + l*256;
            int mm = idx>>4, j4 = (idx&15)*4;
            int kg = ch*64 + j4;
            const float* src;
            if(mode){
                src = &cb[(size_t)(m0+mm)*TD + kg];
            } else {
                src = (kg < 256) ? &g_gr[(m0+mm)*ND + kg] : &g_gi[(m0+mm)*ND + kg - 256];
            }
            float4 v = *(const float4*)src;
            s_x[mm*64+j4+0]=v.x; s_x[mm*64+j4+1]=v.y; s_x[mm*64+j4+2]=v.z; s_x[mm*64+j4+3]=v.w;
        }
        __syncthreads();
        #pragma unroll 4
        for(int j=0;j<64;j++){
            float xv = s_x[ml*64+j];
            #pragma unroll
            for(int i=0;i<8;i++) acc[i] += xv * s_w[(ng+i*8)*65+j];
            if(ng==0) acc[8] += xv * s_w[64*65+j];
        }
    }
    float* outp = mode ? g_alog : g_blog;
    int m = m0 + ml;
    #pragma unroll
    for(int i=0;i<8;i++){
        int n = ng + i*8;
        outp[m*65+n] = acc[i] + ab[n];
    }
    if(ng==0) outp[m*65+64] = acc[8] + gb[0];
}

// ---------------- address finisher (softmax/top-3/gate, all iterations) ------
__global__ void __launch_bounds__(256) k_addr_fin(int use_idx){
    int t = threadIdx.x, wid = t>>5, lane = t&31;
    int b = blockIdx.x*8 + wid;
    const float* row = use_idx ? (g_alog + g_idx[b]*65) : (g_blog + b*65);
    float v0 = row[lane], v1 = row[lane+32];
    float gate = 1.f/(1.f + expf(-row[64]));
    float ent = warp_sum(addr_finish(b, v0, v1, gate, lane));
    __shared__ float s_e[8];
    if(lane==0) s_e[wid] = ent;
    __syncthreads();
    if(t==0){
        float es = 0.f;
        #pragma unroll
        for(int i=0;i<8;i++) es += s_e[i];
        atomicAdd(&g_aux, es*(1.f/(float)NB));
    }
}

// ---- fused assoc-mem (single pass, online softmax) + complex layernorm ------
__global__ void __launch_bounds__(512,2) k_mem(const float* __restrict__ mr_in,
                                               const float* __restrict__ mi_in,
                                               int first,
                                               const float* __restrict__ lnrw, const float* __restrict__ lnrb,
                                               const float* __restrict__ lniw, const float* __restrict__ lnib,
                                               const float* __restrict__ clns, const float* __restrict__ clnb)
{
    __shared__ float s_g[TD];
    __shared__ float s_eff[NS];
    __shared__ float s_part[16*TD];
    __shared__ float s_wm[16];
    __shared__ float s_ws[16];
    __shared__ float s_wscale[17];
    __shared__ float s_red2[16];
    __shared__ float s_scal[2];

    int b = blockIdx.x, t = threadIdx.x, wid = t>>5, lane = t&31;
    const float* mrs = first ? (mr_in + (size_t)b*SD) : (g_mr + (size_t)b*SD);
    const float* mis = first ? (mi_in + (size_t)b*SD) : (g_mi + (size_t)b*SD);

    if(t<ND) s_g[t] = g_gr[b*ND+t]; else s_g[t] = g_gi[b*ND + (t-ND)];
    if(t<NS) s_eff[t] = g_eff[b*NS+t];
    __syncthreads();

    const float4* sg4 = (const float4*)s_g;
    float4 gg0 = sg4[lane], gg1 = sg4[lane+32];
    float4 hh0 = sg4[64+lane], hh1 = sg4[64+lane+32];

    float4 ar0=zero4(), ar1=zero4(), ai0=zero4(), ai1=zero4();
    float om_m = -FLT_MAX, om_s = 0.f;

    #pragma unroll
    for(int r=0;r<4;r++){
        int s = wid*4 + r;
        const float4* pr = (const float4*)(mrs + s*ND);
        const float4* pi = (const float4*)(mis + s*ND);
        float4 a0 = pr[lane], a1 = pr[lane+32];
        float4 c0 = pi[lane], c1 = pi[lane+32];

        float sim = warp_sum(dot4(a0,gg0) + dot4(a1,gg1) + dot4(c0,hh0) + dot4(c1,hh1));

        float mnew = fmaxf(om_m, sim);
        float scale = expf(om_m - mnew);
        float w = expf(sim - mnew);
        scl4(ar0, scale); scl4(ar1, scale); scl4(ai0, scale); scl4(ai1, scale);
        fma4(ar0, w, a0); fma4(ar1, w, a1);
        fma4(ai0, w, c0); fma4(ai1, w, c1);
        om_s = om_s*scale + w;
        om_m = mnew;

        float e = s_eff[s], om = 1.f - e;
        {
            float4 v0 = mix4(om, a0, e, gg0), v1 = mix4(om, a1, e, gg1);
            float mu  = warp_sum(h4(v0)+h4(v1)) * (1.f/ND);
            float var = warp_sum(sq4(v0,mu)+sq4(v1,mu)) * (1.f/ND);
            float inv = 1.f/sqrtf(var + 1e-6f);
            const float4* w4 = (const float4*)lnrw; const float4* b4 = (const float4*)lnrb;
            float4* dst = (float4*)(g_mr + (size_t)b*SD + s*ND);
            dst[lane]    = lnorm4(v0, mu, inv, __ldg(&w4[lane]),    __ldg(&b4[lane]));
            dst[lane+32] = lnorm4(v1, mu, inv, __ldg(&w4[lane+32]), __ldg(&b4[lane+32]));
        }
        {
            float4 v0 = mix4(om, c0, e, hh0), v1 = mix4(om, c1, e, hh1);
            float mu  = warp_sum(h4(v0)+h4(v1)) * (1.f/ND);
            float var = warp_sum(sq4(v0,mu)+sq4(v1,mu)) * (1.f/ND);
            float inv = 1.f/sqrtf(var + 1e-6f);
            const float4* w4 = (const float4*)lniw; const float4* b4 = (const float4*)lnib;
            float4* dst = (float4*)(g_mi + (size_t)b*SD + s*ND);
            dst[lane]    = lnorm4(v0, mu, inv, __ldg(&w4[lane]),    __ldg(&b4[lane]));
            dst[lane+32] = lnorm4(v1, mu, inv, __ldg(&w4[lane+32]), __ldg(&b4[lane+32]));
        }
    }

    {
        float4* sp4 = (float4*)&s_part[wid*TD];
        sp4[lane]    = ar0; sp4[lane+32]    = ar1;
        sp4[64+lane] = ai0; sp4[64+lane+32] = ai1;
        if(lane==0){ s_wm[wid] = om_m; s_ws[wid] = om_s; }
    }
    __syncthreads();

    if(wid==0 && lane==0){
        float M = -FLT_MAX;
        #pragma unroll
        for(int w=0;w<16;w++) M = fmaxf(M, s_wm[w]);
        float total = 0.f;
        #pragma unroll
        for(int w=0;w<16;w++){
            float sc = expf(s_wm[w] - M);
            s_wscale[w] = sc;
            total += s_ws[w]*sc;
        }
        s_wscale[16] = 1.f/total;
    }
    __syncthreads();

    float invt = s_wscale[16];
    float red = 0.f;
    #pragma unroll
    for(int w=0;w<16;w++) red += s_wscale[w]*s_part[w*TD + t];
    red *= invt;
    __syncthreads();
    s_part[t] = red;
    __syncthreads();

    float zr=0.f, zi=0.f, mag=0.f;
    if(t < ND){
        zr = s_g[t]    + s_part[t];
        zi = s_g[ND+t] + s_part[ND+t];
        mag = sqrtf(zr*zr + zi*zi + 1e-8f);
    }
    float p = warp_sum(mag);
    if(lane==0) s_red2[wid] = p;
    __syncthreads();
    if(t==0){
        float m2=0.f;
        #pragma unroll
        for(int i=0;i<8;i++) m2 += s_red2[i];
        s_scal[0] = m2*(1.f/ND);
    }
    __syncthreads();
    float mean = s_scal[0];
    float dv = (t<ND) ? (mag-mean)*(mag-mean) : 0.f;
    p = warp_sum(dv);
    if(lane==0) s_red2[wid] = p;
    __syncthreads();
    if(t==0){
        float v2=0.f;
        #pragma unroll
        for(int i=0;i<8;i++) v2 += s_red2[i];
        s_scal[1] = 1.f/sqrtf(v2*(1.f/(ND-1)) + 1e-4f);
    }
    __syncthreads();
    if(t < ND){
        float nm = (mag-mean)*s_scal[1]*__ldg(&clns[t]) + __ldg(&clnb[t]);
        float h2 = zr*zr + zi*zi;
        float c, s;
        if(h2 > 0.f){ float ih = 1.f/sqrtf(h2); c = zr*ih; s = zi*ih; }
        else { c = 1.f; s = 0.f; }
        float zrv = nm*c, ziv = nm*s;
        size_t zfb = (size_t)b*TD;
        g_zf[zfb + t]      = zrv;
        g_zf[zfb + ND + t] = ziv;
        size_t zbb = (size_t)b*KX;
        __nv_bfloat16 hr = __float2bfloat16_rn(zrv);
        __nv_bfloat16 mr2 = __float2bfloat16_rn(zrv - __bfloat162float(hr));
        g_zb[zbb + t]         = hr;
        g_zb[zbb + 512 + t]   = hr;
        g_zb[zbb + 1024 + t]  = mr2;
        __nv_bfloat16 hi = __float2bfloat16_rn(ziv);
        __nv_bfloat16 mi2 = __float2bfloat16_rn(ziv - __bfloat162float(hi));
        g_zb[zbb + ND + t]        = hi;
        g_zb[zbb + 512 + ND + t]  = hi;
        g_zb[zbb + 1024 + ND + t] = mi2;
    }
}

// ---------------- VQ: bf16 HMMA distance GEMM + argmin ----------------------
// grid (16,16); tile 128 b x 64 k; 8 warps (4x2); warp 32x32; 2 CTA/SM.
#define VQ_A_BYTES 18432     // 128*144
#define VQ_B_BYTES 9216      // 64*144
#define VQ_STG (VQ_A_BYTES+VQ_B_BYTES)   // 27648
__global__ void __launch_bounds__(256,2) k_vq(){
    extern __shared__ char vsm[];   // 2*27648 = 55296 B
    int tid = threadIdx.x, lane = tid&31, wid = tid>>5;
    int g = lane>>2, tig = lane&3;
    int wm = wid>>1, wn = wid&1;
    int b0 = blockIdx.x*128, k0 = blockIdx.y*64;

    float acc[2][4][4];
    #pragma unroll
    for(int i=0;i<2;i++)
        #pragma unroll
        for(int j=0;j<4;j++){ acc[i][j][0]=0.f; acc[i][j][1]=0.f; acc[i][j][2]=0.f; acc[i][j][3]=0.f; }

    #define LOAD_CHUNK(ch, stage) do{ \
        _Pragma("unroll") \
        for(int i=0;i<6;i++){ \
            int q = tid + i*256; \
            if(q < 1024){ \
                int row = q>>3, seg = q&7; \
                cp16(vsm + (stage)*VQ_STG + row*144 + seg*16, \
                     &g_zb[(size_t)(b0+row)*KX + (ch)*64 + seg*8]); \
            } else { \
                int q2 = q-1024; int row = q2>>3, seg = q2&7; \
                cp16(vsm + (stage)*VQ_STG + VQ_A_BYTES + row*144 + seg*16, \
                     &g_cbb[(size_t)(k0+row)*KX + (ch)*64 + seg*8]); \
            } \
        } \
        asm volatile("cp.async.commit_group;"); \
    }while(0)

    LOAD_CHUNK(0, 0);

    for(int ch=0; ch<24; ch++){
        if(ch < 23){
            LOAD_CHUNK(ch+1, (ch+1)&1);
            asm volatile("cp.async.wait_group 1;");
        } else {
            asm volatile("cp.async.wait_group 0;");
        }
        __syncthreads();

        const char* As = vsm + (ch&1)*VQ_STG;
        const char* Bs = As + VQ_A_BYTES;

        #pragma unroll
        for(int kk=0;kk<4;kk++){
            unsigned a[2][4], bfr[4][2];
            #pragma unroll
            for(int m4=0;m4<2;m4++){
                int r = wm*32 + m4*16 + g;
                const char* p = As + r*144 + kk*32 + tig*4;
                a[m4][0] = *(const unsigned*)p;
                a[m4][1] = *(const unsigned*)(p + 8*144);
                a[m4][2] = *(const unsigned*)(p + 16);
                a[m4][3] = *(const unsigned*)(p + 8*144 + 16);
            }
            #pragma unroll
            for(int n4=0;n4<4;n4++){
                int c = wn*32 + n4*8 + g;
                const char* p = Bs + c*144 + kk*32 + tig*4;
                bfr[n4][0] = *(const unsigned*)p;
                bfr[n4][1] = *(const unsigned*)(p + 16);
            }
            #pragma unroll
            for(int m4=0;m4<2;m4++)
                #pragma unroll
                for(int n4=0;n4<4;n4++)
                    mma16(acc[m4][n4], a[m4], bfr[n4]);
        }
        __syncthreads();
    }

    float* s_val = (float*)vsm;             // [128][2]
    int*   s_idx = (int*)(vsm + 1024);      // [128][2]

    float ys[4][2];
    #pragma unroll
    for(int n4=0;n4<4;n4++){
        int c = k0 + wn*32 + n4*8 + tig*2;
        ys[n4][0] = __ldg(&g_ysq[c]);
        ys[n4][1] = __ldg(&g_ysq[c+1]);
    }

    #pragma unroll
    for(int m4=0;m4<2;m4++){
        float bvA = FLT_MAX, bvB = FLT_MAX; int biA = 0x7fffffff, biB = 0x7fffffff;
        #pragma unroll
        for(int n4=0;n4<4;n4++){
            int cb0 = k0 + wn*32 + n4*8 + tig*2;
            float d0 = ys[n4][0] - 2.f*acc[m4][n4][0];
            float d1 = ys[n4][1] - 2.f*acc[m4][n4][1];
            float d2 = ys[n4][0] - 2.f*acc[m4][n4][2];
            float d3 = ys[n4][1] - 2.f*acc[m4][n4][3];
            if(d0 < bvA || (d0==bvA && cb0   < biA)){ bvA = d0; biA = cb0;   }
            if(d1 < bvA || (d1==bvA && cb0+1 < biA)){ bvA = d1; biA = cb0+1; }
            if(d2 < bvB || (d2==bvB && cb0   < biB)){ bvB = d2; biB = cb0;   }
            if(d3 < bvB || (d3==bvB && cb0+1 < biB)){ bvB = d3; biB = cb0+1; }
        }
        #pragma unroll
        for(int o=1;o<4;o<<=1){
            float ovA = __shfl_xor_sync(0xffffffffu, bvA, o);
            int   oiA = __shfl_xor_sync(0xffffffffu, biA, o);
            if(ovA<bvA || (ovA==bvA && oiA<biA)){ bvA=ovA; biA=oiA; }
            float ovB = __shfl_xor_sync(0xffffffffu, bvB, o);
            int   oiB = __shfl_xor_sync(0xffffffffu, biB, o);
            if(ovB<bvB || (ovB==bvB && oiB<biB)){ bvB=ovB; biB=oiB; }
        }
        if(tig==0){
            int rA = wm*32 + m4*16 + g;
            s_val[rA*2+wn]     = bvA; s_idx[rA*2+wn]     = biA;
            s_val[(rA+8)*2+wn] = bvB; s_idx[(rA+8)*2+wn] = biB;
        }
    }
    __syncthreads();
    if(tid < 128){
        float bv = FLT_MAX; int bi = 0x7fffffff;
        #pragma unroll
        for(int j=0;j<2;j++){
            float v = s_val[tid*2+j]; int ix = s_idx[tid*2+j];
            if(v<bv || (v==bv && ix<bi)){ bv=v; bi=ix; }
        }
        g_pscore[(size_t)(b0+tid)*16 + blockIdx.y] = bv;
        g_pidx  [(size_t)(b0+tid)*16 + blockIdx.y] = bi;
    }
    #undef LOAD_CHUNK
}

// ---------------- final argmin, gather codebook, loss, histogram -------------
__global__ void __launch_bounds__(256) k_pick(const float* __restrict__ cb, int it){
    int wid = threadIdx.x>>5, lane = threadIdx.x&31;
    int b = blockIdx.x*8 + wid;
    float bv = FLT_MAX; int bi = 0x7fffffff;
    if(lane < 16){ bv = g_pscore[b*16+lane]; bi = g_pidx[b*16+lane]; }
    #pragma unroll
    for(int o=1;o<32;o<<=1){
        float ov = __shfl_xor_sync(0xffffffffu, bv, o);
        int   oi = __shfl_xor_sync(0xffffffffu, bi, o);
        if(ov<bv || (ov==bv && oi<bi)){ bv=ov; bi=oi; }
    }
    bi = __shfl_sync(0xffffffffu, bi, 0);
    const float* row = cb + (size_t)bi*TD;
    float lacc = 0.f;
    for(int j=lane;j<TD;j+=32){
        float c = row[j], z = g_zf[(size_t)b*TD + j];
        float df = c - z; lacc += df*df;
        if(j < ND) g_gr[b*ND + j] = c;
        else       g_gi[b*ND + j - ND] = c;
    }
    lacc = warp_sum(lacc);
    if(lane==0){
        g_idx[b] = bi;
        atomicAdd(&g_aux, BETA * lacc * (1.f/TD) * (1.f/NB));
        atomicAdd(&g_hist[it*NK + bi], 1);
    }
}

// ---------------- codebook-usage entropy (all 5 iterations) ------------------
__global__ void __launch_bounds__(1024) k_ent5(){
    __shared__ float s_red[32];
    int t = threadIdx.x;
    float e = 0.f;
    #pragma unroll
    for(int it=0;it<5;it++){
        float pp = (float)g_hist[it*NK + t] * (1.f/NB);
        e += -pp * logf(pp + 1e-10f);
    }
    e = warp_sum(e);
    if((t&31)==0) s_red[t>>5] = e;
    __syncthreads();
    if(t < 32){
        float v = s_red[t];
        v = warp_sum(v);
        if(t==0) g_aux = g_aux + v * (1.f/6.931471805599453f);  // /log(1024)
    }
}

// ---------------- write output ----------------
__global__ void k_out(float* __restrict__ out, int out_n){
    int t = blockIdx.x*256 + threadIdx.x;
    int b = t >> 9, j = t & 511;
    out[t] = (j < ND) ? g_gr[b*ND + j] : g_gi[b*ND + j - ND];
    if(t == 0 && out_n > NB*TD) out[out_n-1] = g_aux;
}

// =============================================================================
extern "C" void kernel_launch(void* const* d_in, const int* in_sizes, int n_in,
                              void* d_out, int out_size)
{
    const float* gw_real = (const float*)d_in[0];
    const float* gw_imag = (const float*)d_in[1];
    const float* mem_real= (const float*)d_in[2];
    const float* mem_imag= (const float*)d_in[3];
    const float* gate_w  = (const float*)d_in[4];
    const float* gate_b  = (const float*)d_in[5];
    const float* addr_w  = (const float*)d_in[6];
    const float* addr_b  = (const float*)d_in[7];
    const float* lnr_w   = (const float*)d_in[8];
    const float* lnr_b   = (const float*)d_in[9];
    const float* lni_w   = (const float*)d_in[10];
    const float* lni_b   = (const float*)d_in[11];
    const float* cln_s   = (const float*)d_in[12];
    const float* cln_b   = (const float*)d_in[13];
    const float* codebook= (const float*)d_in[14];
    float* out = (float*)d_out;

    const int SMEM_VQ = 2*VQ_STG;               // 55296
    static int attr_done = 0;
    if(!attr_done){
        cudaFuncSetAttribute(k_vq, cudaFuncAttributeMaxDynamicSharedMemorySize, SMEM_VQ);
        attr_done = 1;
    }

    k_copyg <<<1024, 512>>>(gw_real, gw_imag);
    k_init  <<<128, 256>>>(codebook);
    k_logits<<<32, 256>>>(1, codebook, addr_w, addr_b, gate_w, gate_b);  // g_alog
    k_logits<<<64, 256>>>(0, codebook, addr_w, addr_b, gate_w, gate_b);  // g_blog (iter 0)

    for(int it=0; it<5; it++){
        k_addr_fin<<<256, 256>>>(it==0 ? 0 : 1);
        k_mem <<<NB, 512>>>(mem_real, mem_imag, it==0 ? 1 : 0,
                            lnr_w, lnr_b, lni_w, lni_b, cln_s, cln_b);
        k_vq  <<<dim3(16,16), 256, SMEM_VQ>>>();
        k_pick<<<256, 256>>>(codebook, it);
    }
    k_ent5<<<1, 1024>>>();
    k_out<<<4096, 256>>>(out, out_size);
}

// round 12
// speedup vs baseline: 1.7215x; 1.1495x over previous
#include <cuda_runtime.h>
#include <cuda_bf16.h>
#include <math.h>
#include <float.h>
#include <stdint.h>

#define NB 2048
#define ND 256
#define NS 64
#define NK 1024
#define TD 512          // 2*D
#define SD (NS*ND)      // 16384
#define KX 1536         // 3*TD for bf16x3
#define BETA 0.25f

// ---------------- device scratch ----------------
__device__ float g_mr[(size_t)NB*SD];
__device__ float g_mi[(size_t)NB*SD];
__device__ float g_gr[NB*ND];
__device__ float g_gi[NB*ND];
__device__ float g_zf[(size_t)NB*TD];
__device__ __nv_bfloat16 g_zb[(size_t)NB*KX];   // [zh | zh | zm]
__device__ __nv_bfloat16 g_cbb[(size_t)NK*KX];  // [ch | cm | ch]
__device__ float g_eff[NB*NS];
__device__ float g_ysq[NK];
__device__ float g_alog[NK*65];                 // codebook @ [addr_w|gate_w]
__device__ float g_blog[NB*65];                 // iter-0 logits
__device__ float g_plog[4*NB*65];               // split-K partials
__device__ float g_pscore[NB*16];
__device__ int   g_pidx[NB*16];
__device__ int   g_hist[5*NK];
__device__ float g_aux;

// ---------------- helpers ----------------
__device__ __forceinline__ float warp_sum(float v){
    #pragma unroll
    for(int o=16;o;o>>=1) v += __shfl_xor_sync(0xffffffffu, v, o);
    return v;
}
__device__ __forceinline__ float warp_max(float v){
    #pragma unroll
    for(int o=16;o;o>>=1) v = fmaxf(v, __shfl_xor_sync(0xffffffffu, v, o));
    return v;
}
__device__ __forceinline__ float dot4(float4 a, float4 b){
    return a.x*b.x + a.y*b.y + a.z*b.z + a.w*b.w;
}
__device__ __forceinline__ void fma4(float4& acc, float s, float4 v){
    acc.x += s*v.x; acc.y += s*v.y; acc.z += s*v.z; acc.w += s*v.w;
}
__device__ __forceinline__ void scl4(float4& acc, float s){
    acc.x *= s; acc.y *= s; acc.z *= s; acc.w *= s;
}
__device__ __forceinline__ float4 mix4(float om, float4 a, float e, float4 g){
    float4 r; r.x=om*a.x+e*g.x; r.y=om*a.y+e*g.y; r.z=om*a.z+e*g.z; r.w=om*a.w+e*g.w; return r;
}
__device__ __forceinline__ float h4(float4 v){ return v.x+v.y+v.z+v.w; }
__device__ __forceinline__ float sq4(float4 v, float mu){
    float a=v.x-mu, b=v.y-mu, c=v.z-mu, d=v.w-mu; return a*a+b*b+c*c+d*d;
}
__device__ __forceinline__ float4 lnorm4(float4 v, float mu, float inv, float4 w, float4 b){
    float4 r;
    r.x=(v.x-mu)*inv*w.x+b.x; r.y=(v.y-mu)*inv*w.y+b.y;
    r.z=(v.z-mu)*inv*w.z+b.z; r.w=(v.w-mu)*inv*w.w+b.w; return r;
}
__device__ __forceinline__ float4 zero4(){ float4 z; z.x=z.y=z.z=z.w=0.f; return z; }
__device__ __forceinline__ void cp16(void* dst, const void* src){
    unsigned u = (unsigned)__cvta_generic_to_shared(dst);
    asm volatile("cp.async.cg.shared.global [%0], [%1], 16;" :: "r"(u), "l"(src));
}
__device__ __forceinline__ void mma16(float* d, const unsigned* a, const unsigned* b){
    asm volatile("mma.sync.aligned.m16n8k16.row.col.f32.bf16.bf16.f32 "
        "{%0,%1,%2,%3},{%4,%5,%6,%7},{%8,%9},{%0,%1,%2,%3};"
        : "+f"(d[0]),"+f"(d[1]),"+f"(d[2]),"+f"(d[3])
        : "r"(a[0]),"r"(a[1]),"r"(a[2]),"r"(a[3]),"r"(b[0]),"r"(b[1]));
}

// ---------------- softmax/top3/eff for one b (warp-collective) ---------------
// Returns this lane's PARTIAL entropy — caller must warp_sum.
__device__ __forceinline__ float addr_finish(int b, float v0, float v1, float gate, int lane){
    float m  = warp_max(fmaxf(v0,v1));
    float e0 = expf(v0-m), e1 = expf(v1-m);
    float ssum = warp_sum(e0+e1);
    float w0 = e0/ssum, w1 = e1/ssum;
    float ent = -(w0*logf(w0+1e-10f)) - (w1*logf(w1+1e-10f));
    float a0=w0, a1=w1; int i0=lane, i1=lane+32;
    float tv[3]; int ti[3];
    #pragma unroll
    for(int p3=0;p3<3;p3++){
        float v; int ix;
        if(a0>a1 || (a0==a1 && i0<i1)){ v=a0; ix=i0; } else { v=a1; ix=i1; }
        #pragma unroll
        for(int o=16;o;o>>=1){
            float ov = __shfl_xor_sync(0xffffffffu, v, o);
            int   oi = __shfl_xor_sync(0xffffffffu, ix, o);
            if(ov>v || (ov==v && oi<ix)){ v=ov; ix=oi; }
        }
        tv[p3]=v; ti[p3]=ix;
        if(i0==ix) a0 = -1.f;
        if(i1==ix) a1 = -1.f;
    }
    float norm = 1.f/(tv[0]+tv[1]+tv[2]+1e-6f);
    float o0=0.f, o1=0.f;
    #pragma unroll
    for(int p3=0;p3<3;p3++){
        if(lane==ti[p3])    o0 = tv[p3]*norm;
        if(lane+32==ti[p3]) o1 = tv[p3]*norm;
    }
    g_eff[b*NS+lane]    = gate*o0;
    g_eff[b*NS+lane+32] = gate*o1;
    return ent;
}

// ---------------- copy inputs -> g state ----------------
__global__ void k_copyg(const float* __restrict__ gr, const float* __restrict__ gi){
    int t = blockIdx.x*512 + threadIdx.x;
    g_gr[t] = gr[t];
    g_gi[t] = gi[t];
}

// ---------------- init: ysq, codebook bf16x3 split, zero hist/aux ------------
__global__ void k_init(const float* __restrict__ cb){
    int gt = blockIdx.x*256 + threadIdx.x;
    int w = gt >> 5, lane = gt & 31;
    const float* row = cb + (size_t)w*TD;
    float p = 0.f;
    for(int j=lane;j<TD;j+=32){
        float c = row[j];
        p += c*c;
        __nv_bfloat16 ch = __float2bfloat16_rn(c);
        __nv_bfloat16 cm = __float2bfloat16_rn(c - __bfloat162float(ch));
        size_t base = (size_t)w*KX;
        g_cbb[base + j]        = ch;
        g_cbb[base + 512 + j]  = cm;
        g_cbb[base + 1024 + j] = ch;
    }
    p = warp_sum(p);
    if(lane==0) g_ysq[w] = p;
    if(gt < 5*NK) g_hist[gt] = 0;
    if(gt == 0) g_aux = 0.f;
}

// ---------------- logits GEMM (split-K x4): partials into g_plog ------------
// mode 0: X = initial g, M=2048; mode 1: X = codebook, M=1024.
// grid (M/32, 4); each CTA: 32 rows x 65 outputs over 128-wide K slice.
__global__ void __launch_bounds__(256) k_logits(int mode, const float* __restrict__ cb,
                                                const float* __restrict__ aw,
                                                const float* __restrict__ gw){
    __shared__ float s_w[65*68];
    __shared__ float s_x[32*68];
    int t = threadIdx.x;
    int ml = t >> 3, ng = t & 7;
    int m0 = blockIdx.x*32;
    int kb = blockIdx.y*128;
    float acc[9];
    #pragma unroll
    for(int i=0;i<9;i++) acc[i]=0.f;

    #pragma unroll
    for(int ch=0; ch<2; ch++){
        int k0 = kb + ch*64;
        __syncthreads();
        for(int idx=t; idx<1040; idx+=256){
            int n = idx>>4, j4 = (idx&15)*4;
            float4 v = (n<64) ? *(const float4*)&aw[(size_t)n*TD + k0 + j4]
                              : *(const float4*)&gw[k0 + j4];
            *(float4*)&s_w[n*68+j4] = v;
        }
        #pragma unroll
        for(int l=0;l<2;l++){
            int idx = t + l*256;
            int mm = idx>>4, j4 = (idx&15)*4;
            int kg = k0 + j4;
            const float* src;
            if(mode) src = &cb[(size_t)(m0+mm)*TD + kg];
            else     src = (kg < 256) ? &g_gr[(m0+mm)*ND + kg] : &g_gi[(m0+mm)*ND + kg - 256];
            *(float4*)&s_x[mm*68+j4] = *(const float4*)src;
        }
        __syncthreads();
        #pragma unroll 4
        for(int j=0;j<64;j+=4){
            float4 xv = *(const float4*)&s_x[ml*68+j];
            #pragma unroll
            for(int i=0;i<8;i++){
                float4 wv = *(const float4*)&s_w[(ng+i*8)*68+j];
                acc[i] += dot4(xv, wv);
            }
            if(ng==0){
                float4 wv = *(const float4*)&s_w[64*68+j];
                acc[8] += dot4(xv, wv);
            }
        }
    }
    float* pp = g_plog + blockIdx.y*(NB*65);
    int m = m0 + ml;
    #pragma unroll
    for(int i=0;i<8;i++) pp[m*65 + ng + i*8] = acc[i];
    if(ng==0) pp[m*65 + 64] = acc[8];
}

// ---------------- logits reduce: sum 4 partials + bias ----------------------
__global__ void k_logred(int mode, const float* __restrict__ ab, const float* __restrict__ gb){
    int idx = blockIdx.x*256 + threadIdx.x;
    int M = mode ? NK : NB;
    if(idx >= M*65) return;
    int n = idx - (idx/65)*65;
    float s = g_plog[idx] + g_plog[NB*65+idx] + g_plog[2*NB*65+idx] + g_plog[3*NB*65+idx];
    s += (n < 64) ? ab[n] : gb[0];
    if(mode) g_alog[idx] = s; else g_blog[idx] = s;
}

// ---------------- iter-0 address finisher (from g_blog) ----------------------
__global__ void __launch_bounds__(256) k_addr_fin(){
    int t = threadIdx.x, wid = t>>5, lane = t&31;
    int b = blockIdx.x*8 + wid;
    const float* row = g_blog + b*65;
    float gate = 1.f/(1.f + expf(-row[64]));
    float ent = warp_sum(addr_finish(b, row[lane], row[lane+32], gate, lane));
    __shared__ float s_e[8];
    if(lane==0) s_e[wid] = ent;
    __syncthreads();
    if(t==0){
        float es = 0.f;
        #pragma unroll
        for(int i=0;i<8;i++) es += s_e[i];
        atomicAdd(&g_aux, es*(1.f/(float)NB));
    }
}

// ---- fused assoc-mem (single pass, online softmax) + complex layernorm ------
__global__ void __launch_bounds__(512,2) k_mem(const float* __restrict__ mr_in,
                                               const float* __restrict__ mi_in,
                                               int first,
                                               const float* __restrict__ lnrw, const float* __restrict__ lnrb,
                                               const float* __restrict__ lniw, const float* __restrict__ lnib,
                                               const float* __restrict__ clns, const float* __restrict__ clnb)
{
    __shared__ float s_g[TD];
    __shared__ float s_eff[NS];
    __shared__ float s_part[16*TD];
    __shared__ float s_wm[16];
    __shared__ float s_ws[16];
    __shared__ float s_wscale[17];
    __shared__ float s_red2[16];
    __shared__ float s_scal[2];

    int b = blockIdx.x, t = threadIdx.x, wid = t>>5, lane = t&31;
    const float* mrs = first ? (mr_in + (size_t)b*SD) : (g_mr + (size_t)b*SD);
    const float* mis = first ? (mi_in + (size_t)b*SD) : (g_mi + (size_t)b*SD);

    if(t<ND) s_g[t] = g_gr[b*ND+t]; else s_g[t] = g_gi[b*ND + (t-ND)];
    if(t<NS) s_eff[t] = g_eff[b*NS+t];
    __syncthreads();

    const float4* sg4 = (const float4*)s_g;
    float4 gg0 = sg4[lane], gg1 = sg4[lane+32];
    float4 hh0 = sg4[64+lane], hh1 = sg4[64+lane+32];

    float4 ar0=zero4(), ar1=zero4(), ai0=zero4(), ai1=zero4();
    float om_m = -FLT_MAX, om_s = 0.f;

    #pragma unroll
    for(int r=0;r<4;r++){
        int s = wid*4 + r;
        const float4* pr = (const float4*)(mrs + s*ND);
        const float4* pi = (const float4*)(mis + s*ND);
        float4 a0 = __ldcs(&pr[lane]), a1 = __ldcs(&pr[lane+32]);
        float4 c0 = __ldcs(&pi[lane]), c1 = __ldcs(&pi[lane+32]);

        float sim = warp_sum(dot4(a0,gg0) + dot4(a1,gg1) + dot4(c0,hh0) + dot4(c1,hh1));

        float mnew = fmaxf(om_m, sim);
        float scale = expf(om_m - mnew);
        float w = expf(sim - mnew);
        scl4(ar0, scale); scl4(ar1, scale); scl4(ai0, scale); scl4(ai1, scale);
        fma4(ar0, w, a0); fma4(ar1, w, a1);
        fma4(ai0, w, c0); fma4(ai1, w, c1);
        om_s = om_s*scale + w;
        om_m = mnew;

        float e = s_eff[s], om = 1.f - e;
        {
            float4 v0 = mix4(om, a0, e, gg0), v1 = mix4(om, a1, e, gg1);
            float mu  = warp_sum(h4(v0)+h4(v1)) * (1.f/ND);
            float var = warp_sum(sq4(v0,mu)+sq4(v1,mu)) * (1.f/ND);
            float inv = 1.f/sqrtf(var + 1e-6f);
            const float4* w4 = (const float4*)lnrw; const float4* b4 = (const float4*)lnrb;
            float4* dst = (float4*)(g_mr + (size_t)b*SD + s*ND);
            __stcs(&dst[lane],    lnorm4(v0, mu, inv, __ldg(&w4[lane]),    __ldg(&b4[lane])));
            __stcs(&dst[lane+32], lnorm4(v1, mu, inv, __ldg(&w4[lane+32]), __ldg(&b4[lane+32])));
        }
        {
            float4 v0 = mix4(om, c0, e, hh0), v1 = mix4(om, c1, e, hh1);
            float mu  = warp_sum(h4(v0)+h4(v1)) * (1.f/ND);
            float var = warp_sum(sq4(v0,mu)+sq4(v1,mu)) * (1.f/ND);
            float inv = 1.f/sqrtf(var + 1e-6f);
            const float4* w4 = (const float4*)lniw; const float4* b4 = (const float4*)lnib;
            float4* dst = (float4*)(g_mi + (size_t)b*SD + s*ND);
            __stcs(&dst[lane],    lnorm4(v0, mu, inv, __ldg(&w4[lane]),    __ldg(&b4[lane])));
            __stcs(&dst[lane+32], lnorm4(v1, mu, inv, __ldg(&w4[lane+32]), __ldg(&b4[lane+32])));
        }
    }

    {
        float4* sp4 = (float4*)&s_part[wid*TD];
        sp4[lane]    = ar0; sp4[lane+32]    = ar1;
        sp4[64+lane] = ai0; sp4[64+lane+32] = ai1;
        if(lane==0){ s_wm[wid] = om_m; s_ws[wid] = om_s; }
    }
    __syncthreads();

    if(wid==0 && lane==0){
        float M = -FLT_MAX;
        #pragma unroll
        for(int w=0;w<16;w++) M = fmaxf(M, s_wm[w]);
        float total = 0.f;
        #pragma unroll
        for(int w=0;w<16;w++){
            float sc = expf(s_wm[w] - M);
            s_wscale[w] = sc;
            total += s_ws[w]*sc;
        }
        s_wscale[16] = 1.f/total;
    }
    __syncthreads();

    float invt = s_wscale[16];
    float red = 0.f;
    #pragma unroll
    for(int w=0;w<16;w++) red += s_wscale[w]*s_part[w*TD + t];
    red *= invt;
    __syncthreads();
    s_part[t] = red;
    __syncthreads();

    float zr=0.f, zi=0.f, mag=0.f;
    if(t < ND){
        zr = s_g[t]    + s_part[t];
        zi = s_g[ND+t] + s_part[ND+t];
        mag = sqrtf(zr*zr + zi*zi + 1e-8f);
    }
    float p = warp_sum(mag);
    if(lane==0) s_red2[wid] = p;
    __syncthreads();
    if(t==0){
        float m2=0.f;
        #pragma unroll
        for(int i=0;i<8;i++) m2 += s_red2[i];
        s_scal[0] = m2*(1.f/ND);
    }
    __syncthreads();
    float mean = s_scal[0];
    float dv = (t<ND) ? (mag-mean)*(mag-mean) : 0.f;
    p = warp_sum(dv);
    if(lane==0) s_red2[wid] = p;
    __syncthreads();
    if(t==0){
        float v2=0.f;
        #pragma unroll
        for(int i=0;i<8;i++) v2 += s_red2[i];
        s_scal[1] = 1.f/sqrtf(v2*(1.f/(ND-1)) + 1e-4f);
    }
    __syncthreads();
    if(t < ND){
        float nm = (mag-mean)*s_scal[1]*__ldg(&clns[t]) + __ldg(&clnb[t]);
        float h2 = zr*zr + zi*zi;
        float c, s;
        if(h2 > 0.f){ float ih = 1.f/sqrtf(h2); c = zr*ih; s = zi*ih; }
        else { c = 1.f; s = 0.f; }
        float zrv = nm*c, ziv = nm*s;
        size_t zfb = (size_t)b*TD;
        g_zf[zfb + t]      = zrv;
        g_zf[zfb + ND + t] = ziv;
        size_t zbb = (size_t)b*KX;
        __nv_bfloat16 hr = __float2bfloat16_rn(zrv);
        __nv_bfloat16 mr2 = __float2bfloat16_rn(zrv - __bfloat162float(hr));
        g_zb[zbb + t]         = hr;
        g_zb[zbb + 512 + t]   = hr;
        g_zb[zbb + 1024 + t]  = mr2;
        __nv_bfloat16 hi = __float2bfloat16_rn(ziv);
        __nv_bfloat16 mi2 = __float2bfloat16_rn(ziv - __bfloat162float(hi));
        g_zb[zbb + ND + t]        = hi;
        g_zb[zbb + 512 + ND + t]  = hi;
        g_zb[zbb + 1024 + ND + t] = mi2;
    }
}

// ---------------- VQ: bf16 HMMA distance GEMM + argmin ----------------------
// grid (16,16); tile 128 b x 64 k; 8 warps (4x2); warp 32x32; 2 CTA/SM.
#define VQ_A_BYTES 18432     // 128*144
#define VQ_B_BYTES 9216      // 64*144
#define VQ_STG (VQ_A_BYTES+VQ_B_BYTES)   // 27648
__global__ void __launch_bounds__(256,2) k_vq(){
    extern __shared__ char vsm[];   // 2*27648 = 55296 B
    int tid = threadIdx.x, lane = tid&31, wid = tid>>5;
    int g = lane>>2, tig = lane&3;
    int wm = wid>>1, wn = wid&1;
    int b0 = blockIdx.x*128, k0 = blockIdx.y*64;

    float acc[2][4][4];
    #pragma unroll
    for(int i=0;i<2;i++)
        #pragma unroll
        for(int j=0;j<4;j++){ acc[i][j][0]=0.f; acc[i][j][1]=0.f; acc[i][j][2]=0.f; acc[i][j][3]=0.f; }

    #define LOAD_CHUNK(ch, stage) do{ \
        _Pragma("unroll") \
        for(int i=0;i<6;i++){ \
            int q = tid + i*256; \
            if(q < 1024){ \
                int row = q>>3, seg = q&7; \
                cp16(vsm + (stage)*VQ_STG + row*144 + seg*16, \
                     &g_zb[(size_t)(b0+row)*KX + (ch)*64 + seg*8]); \
            } else { \
                int q2 = q-1024; int row = q2>>3, seg = q2&7; \
                cp16(vsm + (stage)*VQ_STG + VQ_A_BYTES + row*144 + seg*16, \
                     &g_cbb[(size_t)(k0+row)*KX + (ch)*64 + seg*8]); \
            } \
        } \
        asm volatile("cp.async.commit_group;"); \
    }while(0)

    LOAD_CHUNK(0, 0);

    for(int ch=0; ch<24; ch++){
        if(ch < 23){
            LOAD_CHUNK(ch+1, (ch+1)&1);
            asm volatile("cp.async.wait_group 1;");
        } else {
            asm volatile("cp.async.wait_group 0;");
        }
        __syncthreads();

        const char* As = vsm + (ch&1)*VQ_STG;
        const char* Bs = As + VQ_A_BYTES;

        #pragma unroll
        for(int kk=0;kk<4;kk++){
            unsigned a[2][4], bfr[4][2];
            #pragma unroll
            for(int m4=0;m4<2;m4++){
                int r = wm*32 + m4*16 + g;
                const char* p = As + r*144 + kk*32 + tig*4;
                a[m4][0] = *(const unsigned*)p;
                a[m4][1] = *(const unsigned*)(p + 8*144);
                a[m4][2] = *(const unsigned*)(p + 16);
                a[m4][3] = *(const unsigned*)(p + 8*144 + 16);
            }
            #pragma unroll
            for(int n4=0;n4<4;n4++){
                int c = wn*32 + n4*8 + g;
                const char* p = Bs + c*144 + kk*32 + tig*4;
                bfr[n4][0] = *(const unsigned*)p;
                bfr[n4][1] = *(const unsigned*)(p + 16);
            }
            #pragma unroll
            for(int m4=0;m4<2;m4++)
                #pragma unroll
                for(int n4=0;n4<4;n4++)
                    mma16(acc[m4][n4], a[m4], bfr[n4]);
        }
        __syncthreads();
    }

    float* s_val = (float*)vsm;
    int*   s_idx = (int*)(vsm + 1024);

    float ys[4][2];
    #pragma unroll
    for(int n4=0;n4<4;n4++){
        int c = k0 + wn*32 + n4*8 + tig*2;
        ys[n4][0] = __ldg(&g_ysq[c]);
        ys[n4][1] = __ldg(&g_ysq[c+1]);
    }

    #pragma unroll
    for(int m4=0;m4<2;m4++){
        float bvA = FLT_MAX, bvB = FLT_MAX; int biA = 0x7fffffff, biB = 0x7fffffff;
        #pragma unroll
        for(int n4=0;n4<4;n4++){
            int cb0 = k0 + wn*32 + n4*8 + tig*2;
            float d0 = ys[n4][0] - 2.f*acc[m4][n4][0];
            float d1 = ys[n4][1] - 2.f*acc[m4][n4][1];
            float d2 = ys[n4][0] - 2.f*acc[m4][n4][2];
            float d3 = ys[n4][1] - 2.f*acc[m4][n4][3];
            if(d0 < bvA || (d0==bvA && cb0   < biA)){ bvA = d0; biA = cb0;   }
            if(d1 < bvA || (d1==bvA && cb0+1 < biA)){ bvA = d1; biA = cb0+1; }
            if(d2 < bvB || (d2==bvB && cb0   < biB)){ bvB = d2; biB = cb0;   }
            if(d3 < bvB || (d3==bvB && cb0+1 < biB)){ bvB = d3; biB = cb0+1; }
        }
        #pragma unroll
        for(int o=1;o<4;o<<=1){
            float ovA = __shfl_xor_sync(0xffffffffu, bvA, o);
            int   oiA = __shfl_xor_sync(0xffffffffu, biA, o);
            if(ovA<bvA || (ovA==bvA && oiA<biA)){ bvA=ovA; biA=oiA; }
            float ovB = __shfl_xor_sync(0xffffffffu, bvB, o);
            int   oiB = __shfl_xor_sync(0xffffffffu, biB, o);
            if(ovB<bvB || (ovB==bvB && oiB<biB)){ bvB=ovB; biB=oiB; }
        }
        if(tig==0){
            int rA = wm*32 + m4*16 + g;
            s_val[rA*2+wn]     = bvA; s_idx[rA*2+wn]     = biA;
            s_val[(rA+8)*2+wn] = bvB; s_idx[(rA+8)*2+wn] = biB;
        }
    }
    __syncthreads();
    if(tid < 128){
        float bv = FLT_MAX; int bi = 0x7fffffff;
        #pragma unroll
        for(int j=0;j<2;j++){
            float v = s_val[tid*2+j]; int ix = s_idx[tid*2+j];
            if(v<bv || (v==bv && ix<bi)){ bv=v; bi=ix; }
        }
        g_pscore[(size_t)(b0+tid)*16 + blockIdx.y] = bv;
        g_pidx  [(size_t)(b0+tid)*16 + blockIdx.y] = bi;
    }
    #undef LOAD_CHUNK
}

// ------- final argmin, gather, loss, hist + fused next-iter address ----------
__global__ void __launch_bounds__(256) k_pick(const float* __restrict__ cb, int it, int do_addr){
    int wid = threadIdx.x>>5, lane = threadIdx.x&31;
    int b = blockIdx.x*8 + wid;
    float bv = FLT_MAX; int bi = 0x7fffffff;
    if(lane < 16){ bv = g_pscore[b*16+lane]; bi = g_pidx[b*16+lane]; }
    #pragma unroll
    for(int o=1;o<32;o<<=1){
        float ov = __shfl_xor_sync(0xffffffffu, bv, o);
        int   oi = __shfl_xor_sync(0xffffffffu, bi, o);
        if(ov<bv || (ov==bv && oi<bi)){ bv=ov; bi=oi; }
    }
    bi = __shfl_sync(0xffffffffu, bi, 0);
    const float* row = cb + (size_t)bi*TD;
    float lacc = 0.f;
    for(int j=lane;j<TD;j+=32){
        float c = row[j], z = g_zf[(size_t)b*TD + j];
        float df = c - z; lacc += df*df;
        if(j < ND) g_gr[b*ND + j] = c;
        else       g_gi[b*ND + j - ND] = c;
    }
    lacc = warp_sum(lacc);
    if(lane==0){
        atomicAdd(&g_aux, BETA * lacc * (1.f/TD) * (1.f/NB));
        atomicAdd(&g_hist[it*NK + bi], 1);
    }
    if(do_addr){
        const float* lrow = g_alog + bi*65;
        float gate = 1.f/(1.f + expf(-lrow[64]));
        float ent = warp_sum(addr_finish(b, lrow[lane], lrow[lane+32], gate, lane));
        if(lane==0) atomicAdd(&g_aux, ent*(1.f/(float)NB));
    }
}

// ---------------- write output (+ fused codebook-usage entropy) --------------
__global__ void k_out(float* __restrict__ out, int out_n){
    int t0 = threadIdx.x;
    int t = blockIdx.x*256 + t0;
    int b = t >> 9, j = t & 511;
    out[t] = (j < ND) ? g_gr[b*ND + j] : g_gi[b*ND + j - ND];
    if(blockIdx.x == 0){
        __shared__ float s_red[8];
        float e = 0.f;
        for(int q=t0; q<NK; q+=256){
            #pragma unroll
            for(int it=0;it<5;it++){
                float pp = (float)g_hist[it*NK + q] * (1.f/NB);
                e += -pp * logf(pp + 1e-10f);
            }
        }
        e = warp_sum(e);
        if((t0&31)==0) s_red[t0>>5] = e;
        __syncthreads();
        if(t0==0){
            float v = 0.f;
            #pragma unroll
            for(int i=0;i<8;i++) v += s_red[i];
            if(out_n > NB*TD) out[out_n-1] = g_aux + v*(1.f/6.931471805599453f);
        }
    }
}

// =============================================================================
extern "C" void kernel_launch(void* const* d_in, const int* in_sizes, int n_in,
                              void* d_out, int out_size)
{
    const float* gw_real = (const float*)d_in[0];
    const float* gw_imag = (const float*)d_in[1];
    const float* mem_real= (const float*)d_in[2];
    const float* mem_imag= (const float*)d_in[3];
    const float* gate_w  = (const float*)d_in[4];
    const float* gate_b  = (const float*)d_in[5];
    const float* addr_w  = (const float*)d_in[6];
    const float* addr_b  = (const float*)d_in[7];
    const float* lnr_w   = (const float*)d_in[8];
    const float* lnr_b   = (const float*)d_in[9];
    const float* lni_w   = (const float*)d_in[10];
    const float* lni_b   = (const float*)d_in[11];
    const float* cln_s   = (const float*)d_in[12];
    const float* cln_b   = (const float*)d_in[13];
    const float* codebook= (const float*)d_in[14];
    float* out = (float*)d_out;

    const int SMEM_VQ = 2*VQ_STG;               // 55296
    static int attr_done = 0;
    if(!attr_done){
        cudaFuncSetAttribute(k_vq, cudaFuncAttributeMaxDynamicSharedMemorySize, SMEM_VQ);
        attr_done = 1;
    }

    k_copyg <<<1024, 512>>>(gw_real, gw_imag);
    k_init  <<<128, 256>>>(codebook);
    k_logits<<<dim3(32,4), 256>>>(1, codebook, addr_w, gate_w);
    k_logred<<<(NK*65+255)/256, 256>>>(1, addr_b, gate_b);
    k_logits<<<dim3(64,4), 256>>>(0, codebook, addr_w, gate_w);
    k_logred<<<(NB*65+255)/256, 256>>>(0, addr_b, gate_b);
    k_addr_fin<<<256, 256>>>();

    for(int it=0; it<5; it++){
        k_mem <<<NB, 512>>>(mem_real, mem_imag, it==0 ? 1 : 0,
                            lnr_w, lnr_b, lni_w, lni_b, cln_s, cln_b);
        k_vq  <<<dim3(16,16), 256, SMEM_VQ>>>();
        k_pick<<<256, 256>>>(codebook, it, it<4 ? 1 : 0);
    }
    k_out<<<4096, 256>>>(out, out_size);
}

// round 13
// speedup vs baseline: 1.8692x; 1.0857x over previous
#include <cuda_runtime.h>
#include <cuda_bf16.h>
#include <math.h>
#include <float.h>
#include <stdint.h>

#define NB 2048
#define ND 256
#define NS 64
#define NK 1024
#define TD 512          // 2*D
#define SD (NS*ND)      // 16384
#define KX 1536         // 3*TD for bf16x3
#define BETA 0.25f

// ---------------- device scratch ----------------
__device__ float g_mr[(size_t)NB*SD];
__device__ float g_mi[(size_t)NB*SD];
__device__ float g_gr[NB*ND];
__device__ float g_gi[NB*ND];
__device__ float g_zf[(size_t)NB*TD];
__device__ __nv_bfloat16 g_zb[(size_t)NB*KX];   // [zh | zh | zm]
__device__ __nv_bfloat16 g_cbb[(size_t)NK*KX];  // [ch | cm | ch]
__device__ float g_eff[NB*NS];
__device__ float g_ysq[NK];
__device__ float g_alog[NK*65];
__device__ float g_blog[NB*65];
__device__ float g_plog[4*NB*65];
__device__ float g_pscore[NB*16];
__device__ int   g_pidx[NB*16];
__device__ int   g_hist[5*NK];
__device__ float g_aux;

// ---------------- helpers ----------------
__device__ __forceinline__ float warp_sum(float v){
    #pragma unroll
    for(int o=16;o;o>>=1) v += __shfl_xor_sync(0xffffffffu, v, o);
    return v;
}
__device__ __forceinline__ void warp_sum2(float& a, float& b){
    #pragma unroll
    for(int o=16;o;o>>=1){
        a += __shfl_xor_sync(0xffffffffu, a, o);
        b += __shfl_xor_sync(0xffffffffu, b, o);
    }
}
__device__ __forceinline__ float warp_max(float v){
    #pragma unroll
    for(int o=16;o;o>>=1) v = fmaxf(v, __shfl_xor_sync(0xffffffffu, v, o));
    return v;
}
__device__ __forceinline__ float dot4(float4 a, float4 b){
    return a.x*b.x + a.y*b.y + a.z*b.z + a.w*b.w;
}
__device__ __forceinline__ void fma4(float4& acc, float s, float4 v){
    acc.x += s*v.x; acc.y += s*v.y; acc.z += s*v.z; acc.w += s*v.w;
}
__device__ __forceinline__ void scl4(float4& acc, float s){
    acc.x *= s; acc.y *= s; acc.z *= s; acc.w *= s;
}
__device__ __forceinline__ float4 mix4(float om, float4 a, float e, float4 g){
    float4 r; r.x=om*a.x+e*g.x; r.y=om*a.y+e*g.y; r.z=om*a.z+e*g.z; r.w=om*a.w+e*g.w; return r;
}
__device__ __forceinline__ float h4(float4 v){ return v.x+v.y+v.z+v.w; }
__device__ __forceinline__ float ss4(float4 v){
    return v.x*v.x + v.y*v.y + v.z*v.z + v.w*v.w;
}
__device__ __forceinline__ float4 lnorm4(float4 v, float mu, float inv, float4 w, float4 b){
    float4 r;
    r.x=(v.x-mu)*inv*w.x+b.x; r.y=(v.y-mu)*inv*w.y+b.y;
    r.z=(v.z-mu)*inv*w.z+b.z; r.w=(v.w-mu)*inv*w.w+b.w; return r;
}
__device__ __forceinline__ float4 zero4(){ float4 z; z.x=z.y=z.z=z.w=0.f; return z; }
__device__ __forceinline__ void cp16(void* dst, const void* src){
    unsigned u = (unsigned)__cvta_generic_to_shared(dst);
    asm volatile("cp.async.cg.shared.global [%0], [%1], 16;" :: "r"(u), "l"(src));
}
__device__ __forceinline__ void mma16(float* d, const unsigned* a, const unsigned* b){
    asm volatile("mma.sync.aligned.m16n8k16.row.col.f32.bf16.bf16.f32 "
        "{%0,%1,%2,%3},{%4,%5,%6,%7},{%8,%9},{%0,%1,%2,%3};"
        : "+f"(d[0]),"+f"(d[1]),"+f"(d[2]),"+f"(d[3])
        : "r"(a[0]),"r"(a[1]),"r"(a[2]),"r"(a[3]),"r"(b[0]),"r"(b[1]));
}

// ---------------- softmax/top3/eff (warp-collective, returns lane-partial ent)
__device__ __forceinline__ float addr_finish(int b, float v0, float v1, float gate, int lane){
    float m  = warp_max(fmaxf(v0,v1));
    float e0 = expf(v0-m), e1 = expf(v1-m);
    float ssum = warp_sum(e0+e1);
    float w0 = e0/ssum, w1 = e1/ssum;
    float ent = -(w0*logf(w0+1e-10f)) - (w1*logf(w1+1e-10f));
    float a0=w0, a1=w1; int i0=lane, i1=lane+32;
    float tv[3]; int ti[3];
    #pragma unroll
    for(int p3=0;p3<3;p3++){
        float v; int ix;
        if(a0>a1 || (a0==a1 && i0<i1)){ v=a0; ix=i0; } else { v=a1; ix=i1; }
        #pragma unroll
        for(int o=16;o;o>>=1){
            float ov = __shfl_xor_sync(0xffffffffu, v, o);
            int   oi = __shfl_xor_sync(0xffffffffu, ix, o);
            if(ov>v || (ov==v && oi<ix)){ v=ov; ix=oi; }
        }
        tv[p3]=v; ti[p3]=ix;
        if(i0==ix) a0 = -1.f;
        if(i1==ix) a1 = -1.f;
    }
    float norm = 1.f/(tv[0]+tv[1]+tv[2]+1e-6f);
    float o0=0.f, o1=0.f;
    #pragma unroll
    for(int p3=0;p3<3;p3++){
        if(lane==ti[p3])    o0 = tv[p3]*norm;
        if(lane+32==ti[p3]) o1 = tv[p3]*norm;
    }
    g_eff[b*NS+lane]    = gate*o0;
    g_eff[b*NS+lane+32] = gate*o1;
    return ent;
}

// ---------------- init: ysq, codebook bf16x3 split, zero hist/aux ------------
__global__ void k_init(const float* __restrict__ cb){
    int gt = blockIdx.x*256 + threadIdx.x;
    int w = gt >> 5, lane = gt & 31;
    const float* row = cb + (size_t)w*TD;
    float p = 0.f;
    for(int j=lane;j<TD;j+=32){
        float c = row[j];
        p += c*c;
        __nv_bfloat16 ch = __float2bfloat16_rn(c);
        __nv_bfloat16 cm = __float2bfloat16_rn(c - __bfloat162float(ch));
        size_t base = (size_t)w*KX;
        g_cbb[base + j]        = ch;
        g_cbb[base + 512 + j]  = cm;
        g_cbb[base + 1024 + j] = ch;
    }
    p = warp_sum(p);
    if(lane==0) g_ysq[w] = p;
    if(gt < 5*NK) g_hist[gt] = 0;
    if(gt == 0) g_aux = 0.f;
}

// ---------------- logits GEMM (split-K x4) ----------------------------------
__global__ void __launch_bounds__(256) k_logits(int mode, const float* __restrict__ cb,
                                                const float* __restrict__ gr_in,
                                                const float* __restrict__ gi_in,
                                                const float* __restrict__ aw,
                                                const float* __restrict__ gw){
    __shared__ float s_w[65*68];
    __shared__ float s_x[32*68];
    int t = threadIdx.x;
    int ml = t >> 3, ng = t & 7;
    int m0 = blockIdx.x*32;
    int kb = blockIdx.y*128;
    float acc[9];
    #pragma unroll
    for(int i=0;i<9;i++) acc[i]=0.f;

    #pragma unroll
    for(int ch=0; ch<2; ch++){
        int k0 = kb + ch*64;
        __syncthreads();
        for(int idx=t; idx<1040; idx+=256){
            int n = idx>>4, j4 = (idx&15)*4;
            float4 v = (n<64) ? *(const float4*)&aw[(size_t)n*TD + k0 + j4]
                              : *(const float4*)&gw[k0 + j4];
            *(float4*)&s_w[n*68+j4] = v;
        }
        #pragma unroll
        for(int l=0;l<2;l++){
            int idx = t + l*256;
            int mm = idx>>4, j4 = (idx&15)*4;
            int kg = k0 + j4;
            const float* src;
            if(mode) src = &cb[(size_t)(m0+mm)*TD + kg];
            else     src = (kg < 256) ? &gr_in[(m0+mm)*ND + kg] : &gi_in[(m0+mm)*ND + kg - 256];
            *(float4*)&s_x[mm*68+j4] = *(const float4*)src;
        }
        __syncthreads();
        #pragma unroll 4
        for(int j=0;j<64;j+=4){
            float4 xv = *(const float4*)&s_x[ml*68+j];
            #pragma unroll
            for(int i=0;i<8;i++){
                float4 wv = *(const float4*)&s_w[(ng+i*8)*68+j];
                acc[i] += dot4(xv, wv);
            }
            if(ng==0){
                float4 wv = *(const float4*)&s_w[64*68+j];
                acc[8] += dot4(xv, wv);
            }
        }
    }
    float* pp = g_plog + blockIdx.y*(NB*65);
    int m = m0 + ml;
    #pragma unroll
    for(int i=0;i<8;i++) pp[m*65 + ng + i*8] = acc[i];
    if(ng==0) pp[m*65 + 64] = acc[8];
}

// ---------------- logits reduce ----------------------------------------------
__global__ void k_logred(int mode, const float* __restrict__ ab, const float* __restrict__ gb){
    int idx = blockIdx.x*256 + threadIdx.x;
    int M = mode ? NK : NB;
    if(idx >= M*65) return;
    int n = idx - (idx/65)*65;
    float s = g_plog[idx] + g_plog[NB*65+idx] + g_plog[2*NB*65+idx] + g_plog[3*NB*65+idx];
    s += (n < 64) ? ab[n] : gb[0];
    if(mode) g_alog[idx] = s; else g_blog[idx] = s;
}

// ---------------- iter-0 address finisher ------------------------------------
__global__ void __launch_bounds__(256) k_addr_fin(){
    int t = threadIdx.x, wid = t>>5, lane = t&31;
    int b = blockIdx.x*8 + wid;
    const float* row = g_blog + b*65;
    float gate = 1.f/(1.f + expf(-row[64]));
    float ent = warp_sum(addr_finish(b, row[lane], row[lane+32], gate, lane));
    __shared__ float s_e[8];
    if(lane==0) s_e[wid] = ent;
    __syncthreads();
    if(t==0){
        float es = 0.f;
        #pragma unroll
        for(int i=0;i<8;i++) es += s_e[i];
        atomicAdd(&g_aux, es*(1.f/(float)NB));
    }
}

// ---- fused assoc-mem (single pass, online softmax) + complex layernorm ------
__global__ void __launch_bounds__(512,2) k_mem(const float* __restrict__ mr_in,
                                               const float* __restrict__ mi_in,
                                               const float* __restrict__ gr_in,
                                               const float* __restrict__ gi_in,
                                               int first, int last,
                                               const float* __restrict__ lnrw, const float* __restrict__ lnrb,
                                               const float* __restrict__ lniw, const float* __restrict__ lnib,
                                               const float* __restrict__ clns, const float* __restrict__ clnb)
{
    __shared__ float s_g[TD];
    __shared__ float s_eff[NS];
    __shared__ float s_part[16*TD];
    __shared__ float s_wm[16];
    __shared__ float s_ws[16];
    __shared__ float s_wscale[17];
    __shared__ float s_red2[16];
    __shared__ float s_scal[2];

    int b = blockIdx.x, t = threadIdx.x, wid = t>>5, lane = t&31;
    const float* mrs = first ? (mr_in + (size_t)b*SD) : (g_mr + (size_t)b*SD);
    const float* mis = first ? (mi_in + (size_t)b*SD) : (g_mi + (size_t)b*SD);

    if(t<ND) s_g[t] = first ? gr_in[b*ND+t] : g_gr[b*ND+t];
    else     s_g[t] = first ? gi_in[b*ND + (t-ND)] : g_gi[b*ND + (t-ND)];
    if(t<NS) s_eff[t] = g_eff[b*NS+t];
    __syncthreads();

    const float4* sg4 = (const float4*)s_g;
    float4 gg0 = sg4[lane], gg1 = sg4[lane+32];
    float4 hh0 = sg4[64+lane], hh1 = sg4[64+lane+32];

    float4 ar0=zero4(), ar1=zero4(), ai0=zero4(), ai1=zero4();
    float om_m = -FLT_MAX, om_s = 0.f;

    #pragma unroll
    for(int r=0;r<4;r++){
        int s = wid*4 + r;
        const float4* pr = (const float4*)(mrs + s*ND);
        const float4* pi = (const float4*)(mis + s*ND);
        float4 a0 = __ldcs(&pr[lane]), a1 = __ldcs(&pr[lane+32]);
        float4 c0 = __ldcs(&pi[lane]), c1 = __ldcs(&pi[lane+32]);

        float sim = warp_sum(dot4(a0,gg0) + dot4(a1,gg1) + dot4(c0,hh0) + dot4(c1,hh1));

        float mnew = fmaxf(om_m, sim);
        float scale = expf(om_m - mnew);
        float w = expf(sim - mnew);
        scl4(ar0, scale); scl4(ar1, scale); scl4(ai0, scale); scl4(ai1, scale);
        fma4(ar0, w, a0); fma4(ar1, w, a1);
        fma4(ai0, w, c0); fma4(ai1, w, c1);
        om_s = om_s*scale + w;
        om_m = mnew;

        if(!last){
            float e = s_eff[s], om = 1.f - e;
            {
                float4 v0 = mix4(om, a0, e, gg0), v1 = mix4(om, a1, e, gg1);
                float sv = h4(v0)+h4(v1), sq = ss4(v0)+ss4(v1);
                warp_sum2(sv, sq);
                float mu  = sv*(1.f/ND);
                float var = sq*(1.f/ND) - mu*mu;
                float inv = 1.f/sqrtf(var + 1e-6f);
                const float4* w4 = (const float4*)lnrw; const float4* b4 = (const float4*)lnrb;
                float4* dst = (float4*)(g_mr + (size_t)b*SD + s*ND);
                __stcs(&dst[lane],    lnorm4(v0, mu, inv, __ldg(&w4[lane]),    __ldg(&b4[lane])));
                __stcs(&dst[lane+32], lnorm4(v1, mu, inv, __ldg(&w4[lane+32]), __ldg(&b4[lane+32])));
            }
            {
                float4 v0 = mix4(om, c0, e, hh0), v1 = mix4(om, c1, e, hh1);
                float sv = h4(v0)+h4(v1), sq = ss4(v0)+ss4(v1);
                warp_sum2(sv, sq);
                float mu  = sv*(1.f/ND);
                float var = sq*(1.f/ND) - mu*mu;
                float inv = 1.f/sqrtf(var + 1e-6f);
                const float4* w4 = (const float4*)lniw; const float4* b4 = (const float4*)lnib;
                float4* dst = (float4*)(g_mi + (size_t)b*SD + s*ND);
                __stcs(&dst[lane],    lnorm4(v0, mu, inv, __ldg(&w4[lane]),    __ldg(&b4[lane])));
                __stcs(&dst[lane+32], lnorm4(v1, mu, inv, __ldg(&w4[lane+32]), __ldg(&b4[lane+32])));
            }
        }
    }

    {
        float4* sp4 = (float4*)&s_part[wid*TD];
        sp4[lane]    = ar0; sp4[lane+32]    = ar1;
        sp4[64+lane] = ai0; sp4[64+lane+32] = ai1;
        if(lane==0){ s_wm[wid] = om_m; s_ws[wid] = om_s; }
    }
    __syncthreads();

    if(wid==0 && lane==0){
        float M = -FLT_MAX;
        #pragma unroll
        for(int w=0;w<16;w++) M = fmaxf(M, s_wm[w]);
        float total = 0.f;
        #pragma unroll
        for(int w=0;w<16;w++){
            float sc = expf(s_wm[w] - M);
            s_wscale[w] = sc;
            total += s_ws[w]*sc;
        }
        s_wscale[16] = 1.f/total;
    }
    __syncthreads();

    float invt = s_wscale[16];
    float red = 0.f;
    #pragma unroll
    for(int w=0;w<16;w++) red += s_wscale[w]*s_part[w*TD + t];
    red *= invt;
    __syncthreads();
    s_part[t] = red;
    __syncthreads();

    float zr=0.f, zi=0.f, mag=0.f;
    if(t < ND){
        zr = s_g[t]    + s_part[t];
        zi = s_g[ND+t] + s_part[ND+t];
        mag = sqrtf(zr*zr + zi*zi + 1e-8f);
    }
    float p = warp_sum(mag);
    if(lane==0) s_red2[wid] = p;
    __syncthreads();
    if(t==0){
        float m2=0.f;
        #pragma unroll
        for(int i=0;i<8;i++) m2 += s_red2[i];
        s_scal[0] = m2*(1.f/ND);
    }
    __syncthreads();
    float mean = s_scal[0];
    float dv = (t<ND) ? (mag-mean)*(mag-mean) : 0.f;
    p = warp_sum(dv);
    if(lane==0) s_red2[wid] = p;
    __syncthreads();
    if(t==0){
        float v2=0.f;
        #pragma unroll
        for(int i=0;i<8;i++) v2 += s_red2[i];
        s_scal[1] = 1.f/sqrtf(v2*(1.f/(ND-1)) + 1e-4f);
    }
    __syncthreads();
    if(t < ND){
        float nm = (mag-mean)*s_scal[1]*__ldg(&clns[t]) + __ldg(&clnb[t]);
        float h2 = zr*zr + zi*zi;
        float c, s;
        if(h2 > 0.f){ float ih = 1.f/sqrtf(h2); c = zr*ih; s = zi*ih; }
        else { c = 1.f; s = 0.f; }
        float zrv = nm*c, ziv = nm*s;
        size_t zfb = (size_t)b*TD;
        g_zf[zfb + t]      = zrv;
        g_zf[zfb + ND + t] = ziv;
        size_t zbb = (size_t)b*KX;
        __nv_bfloat16 hr = __float2bfloat16_rn(zrv);
        __nv_bfloat16 mr2 = __float2bfloat16_rn(zrv - __bfloat162float(hr));
        g_zb[zbb + t]         = hr;
        g_zb[zbb + 512 + t]   = hr;
        g_zb[zbb + 1024 + t]  = mr2;
        __nv_bfloat16 hi = __float2bfloat16_rn(ziv);
        __nv_bfloat16 mi2 = __float2bfloat16_rn(ziv - __bfloat162float(hi));
        g_zb[zbb + ND + t]        = hi;
        g_zb[zbb + 512 + ND + t]  = hi;
        g_zb[zbb + 1024 + ND + t] = mi2;
    }
}

// ---------------- VQ: bf16 HMMA distance GEMM + argmin ----------------------
#define VQ_A_BYTES 18432
#define VQ_B_BYTES 9216
#define VQ_STG (VQ_A_BYTES+VQ_B_BYTES)
__global__ void __launch_bounds__(256,2) k_vq(){
    extern __shared__ char vsm[];
    int tid = threadIdx.x, lane = tid&31, wid = tid>>5;
    int g = lane>>2, tig = lane&3;
    int wm = wid>>1, wn = wid&1;
    int b0 = blockIdx.x*128, k0 = blockIdx.y*64;

    float acc[2][4][4];
    #pragma unroll
    for(int i=0;i<2;i++)
        #pragma unroll
        for(int j=0;j<4;j++){ acc[i][j][0]=0.f; acc[i][j][1]=0.f; acc[i][j][2]=0.f; acc[i][j][3]=0.f; }

    #define LOAD_CHUNK(ch, stage) do{ \
        _Pragma("unroll") \
        for(int i=0;i<6;i++){ \
            int q = tid + i*256; \
            if(q < 1024){ \
                int row = q>>3, seg = q&7; \
                cp16(vsm + (stage)*VQ_STG + row*144 + seg*16, \
                     &g_zb[(size_t)(b0+row)*KX + (ch)*64 + seg*8]); \
            } else { \
                int q2 = q-1024; int row = q2>>3, seg = q2&7; \
                cp16(vsm + (stage)*VQ_STG + VQ_A_BYTES + row*144 + seg*16, \
                     &g_cbb[(size_t)(k0+row)*KX + (ch)*64 + seg*8]); \
            } \
        } \
        asm volatile("cp.async.commit_group;"); \
    }while(0)

    LOAD_CHUNK(0, 0);

    for(int ch=0; ch<24; ch++){
        if(ch < 23){
            LOAD_CHUNK(ch+1, (ch+1)&1);
            asm volatile("cp.async.wait_group 1;");
        } else {
            asm volatile("cp.async.wait_group 0;");
        }
        __syncthreads();

        const char* As = vsm + (ch&1)*VQ_STG;
        const char* Bs = As + VQ_A_BYTES;

        #pragma unroll
        for(int kk=0;kk<4;kk++){
            unsigned a[2][4], bfr[4][2];
            #pragma unroll
            for(int m4=0;m4<2;m4++){
                int r = wm*32 + m4*16 + g;
                const char* p = As + r*144 + kk*32 + tig*4;
                a[m4][0] = *(const unsigned*)p;
                a[m4][1] = *(const unsigned*)(p + 8*144);
                a[m4][2] = *(const unsigned*)(p + 16);
                a[m4][3] = *(const unsigned*)(p + 8*144 + 16);
            }
            #pragma unroll
            for(int n4=0;n4<4;n4++){
                int c = wn*32 + n4*8 + g;
                const char* p = Bs + c*144 + kk*32 + tig*4;
                bfr[n4][0] = *(const unsigned*)p;
                bfr[n4][1] = *(const unsigned*)(p + 16);
            }
            #pragma unroll
            for(int m4=0;m4<2;m4++)
                #pragma unroll
                for(int n4=0;n4<4;n4++)
                    mma16(acc[m4][n4], a[m4], bfr[n4]);
        }
        __syncthreads();
    }

    float* s_val = (float*)vsm;
    int*   s_idx = (int*)(vsm + 1024);

    float ys[4][2];
    #pragma unroll
    for(int n4=0;n4<4;n4++){
        int c = k0 + wn*32 + n4*8 + tig*2;
        ys[n4][0] = __ldg(&g_ysq[c]);
        ys[n4][1] = __ldg(&g_ysq[c+1]);
    }

    #pragma unroll
    for(int m4=0;m4<2;m4++){
        float bvA = FLT_MAX, bvB = FLT_MAX; int biA = 0x7fffffff, biB = 0x7fffffff;
        #pragma unroll
        for(int n4=0;n4<4;n4++){
            int cb0 = k0 + wn*32 + n4*8 + tig*2;
            float d0 = ys[n4][0] - 2.f*acc[m4][n4][0];
            float d1 = ys[n4][1] - 2.f*acc[m4][n4][1];
            float d2 = ys[n4][0] - 2.f*acc[m4][n4][2];
            float d3 = ys[n4][1] - 2.f*acc[m4][n4][3];
            if(d0 < bvA || (d0==bvA && cb0   < biA)){ bvA = d0; biA = cb0;   }
            if(d1 < bvA || (d1==bvA && cb0+1 < biA)){ bvA = d1; biA = cb0+1; }
            if(d2 < bvB || (d2==bvB && cb0   < biB)){ bvB = d2; biB = cb0;   }
            if(d3 < bvB || (d3==bvB && cb0+1 < biB)){ bvB = d3; biB = cb0+1; }
        }
        #pragma unroll
        for(int o=1;o<4;o<<=1){
            float ovA = __shfl_xor_sync(0xffffffffu, bvA, o);
            int   oiA = __shfl_xor_sync(0xffffffffu, biA, o);
            if(ovA<bvA || (ovA==bvA && oiA<biA)){ bvA=ovA; biA=oiA; }
            float ovB = __shfl_xor_sync(0xffffffffu, bvB, o);
            int   oiB = __shfl_xor_sync(0xffffffffu, biB, o);
            if(ovB<bvB || (ovB==bvB && oiB<biB)){ bvB=ovB; biB=oiB; }
        }
        if(tig==0){
            int rA = wm*32 + m4*16 + g;
            s_val[rA*2+wn]     = bvA; s_idx[rA*2+wn]     = biA;
            s_val[(rA+8)*2+wn] = bvB; s_idx[(rA+8)*2+wn] = biB;
        }
    }
    __syncthreads();
    if(tid < 128){
        float bv = FLT_MAX; int bi = 0x7fffffff;
        #pragma unroll
        for(int j=0;j<2;j++){
            float v = s_val[tid*2+j]; int ix = s_idx[tid*2+j];
            if(v<bv || (v==bv && ix<bi)){ bv=v; bi=ix; }
        }
        g_pscore[(size_t)(b0+tid)*16 + blockIdx.y] = bv;
        g_pidx  [(size_t)(b0+tid)*16 + blockIdx.y] = bi;
    }
    #undef LOAD_CHUNK
}

// ------- final argmin, gather, loss, hist + fused next-iter address ----------
__global__ void __launch_bounds__(256) k_pick(const float* __restrict__ cb, int it, int do_addr){
    int wid = threadIdx.x>>5, lane = threadIdx.x&31;
    int b = blockIdx.x*8 + wid;
    float bv = FLT_MAX; int bi = 0x7fffffff;
    if(lane < 16){ bv = g_pscore[b*16+lane]; bi = g_pidx[b*16+lane]; }
    #pragma unroll
    for(int o=1;o<32;o<<=1){
        float ov = __shfl_xor_sync(0xffffffffu, bv, o);
        int   oi = __shfl_xor_sync(0xffffffffu, bi, o);
        if(ov<bv || (ov==bv && oi<bi)){ bv=ov; bi=oi; }
    }
    bi = __shfl_sync(0xffffffffu, bi, 0);
    const float* row = cb + (size_t)bi*TD;
    float lacc = 0.f;
    for(int j=lane;j<TD;j+=32){
        float c = row[j], z = g_zf[(size_t)b*TD + j];
        float df = c - z; lacc += df*df;
        if(j < ND) g_gr[b*ND + j] = c;
        else       g_gi[b*ND + j - ND] = c;
    }
    lacc = warp_sum(lacc);
    if(lane==0){
        atomicAdd(&g_aux, BETA * lacc * (1.f/TD) * (1.f/NB));
        atomicAdd(&g_hist[it*NK + bi], 1);
    }
    if(do_addr){
        const float* lrow = g_alog + bi*65;
        float gate = 1.f/(1.f + expf(-lrow[64]));
        float ent = warp_sum(addr_finish(b, lrow[lane], lrow[lane+32], gate, lane));
        if(lane==0) atomicAdd(&g_aux, ent*(1.f/(float)NB));
    }
}

// ---------------- write output (+ fused codebook-usage entropy) --------------
__global__ void k_out(float* __restrict__ out, int out_n){
    int t0 = threadIdx.x;
    int t = blockIdx.x*256 + t0;
    int b = t >> 9, j = t & 511;
    out[t] = (j < ND) ? g_gr[b*ND + j] : g_gi[b*ND + j - ND];
    if(blockIdx.x == 0){
        __shared__ float s_red[8];
        float e = 0.f;
        for(int q=t0; q<NK; q+=256){
            #pragma unroll
            for(int it=0;it<5;it++){
                float pp = (float)g_hist[it*NK + q] * (1.f/NB);
                e += -pp * logf(pp + 1e-10f);
            }
        }
        e = warp_sum(e);
        if((t0&31)==0) s_red[t0>>5] = e;
        __syncthreads();
        if(t0==0){
            float v = 0.f;
            #pragma unroll
            for(int i=0;i<8;i++) v += s_red[i];
            if(out_n > NB*TD) out[out_n-1] = g_aux + v*(1.f/6.931471805599453f);
        }
    }
}

// =============================================================================
extern "C" void kernel_launch(void* const* d_in, const int* in_sizes, int n_in,
                              void* d_out, int out_size)
{
    const float* gw_real = (const float*)d_in[0];
    const float* gw_imag = (const float*)d_in[1];
    const float* mem_real= (const float*)d_in[2];
    const float* mem_imag= (const float*)d_in[3];
    const float* gate_w  = (const float*)d_in[4];
    const float* gate_b  = (const float*)d_in[5];
    const float* addr_w  = (const float*)d_in[6];
    const float* addr_b  = (const float*)d_in[7];
    const float* lnr_w   = (const float*)d_in[8];
    const float* lnr_b   = (const float*)d_in[9];
    const float* lni_w   = (const float*)d_in[10];
    const float* lni_b   = (const float*)d_in[11];
    const float* cln_s   = (const float*)d_in[12];
    const float* cln_b   = (const float*)d_in[13];
    const float* codebook= (const float*)d_in[14];
    float* out = (float*)d_out;

    const int SMEM_VQ = 2*VQ_STG;
    static int attr_done = 0;
    if(!attr_done){
        cudaFuncSetAttribute(k_vq, cudaFuncAttributeMaxDynamicSharedMemorySize, SMEM_VQ);
        attr_done = 1;
    }

    k_init  <<<128, 256>>>(codebook);
    k_logits<<<dim3(32,4), 256>>>(1, codebook, gw_real, gw_imag, addr_w, gate_w);
    k_logred<<<(NK*65+255)/256, 256>>>(1, addr_b, gate_b);
    k_logits<<<dim3(64,4), 256>>>(0, codebook, gw_real, gw_imag, addr_w, gate_w);
    k_logred<<<(NB*65+255)/256, 256>>>(0, addr_b, gate_b);
    k_addr_fin<<<256, 256>>>();

    for(int it=0; it<5; it++){
        k_mem <<<NB, 512>>>(mem_real, mem_imag, gw_real, gw_imag,
                            it==0 ? 1 : 0, it==4 ? 1 : 0,
                            lnr_w, lnr_b, lni_w, lni_b, cln_s, cln_b);
        k_vq  <<<dim3(16,16), 256, SMEM_VQ>>>();
        k_pick<<<256, 256>>>(codebook, it, it<4 ? 1 : 0);
    }
    k_out<<<4096, 256>>>(out, out_size);
}